// round 1
// baseline (speedup 1.0000x reference)
#include <cuda_runtime.h>
#include <cstdint>

// Problem constants
#define BB   4
#define CC   512
#define NN   1024
#define HH   8
#define DD   64
#define BHH  32   // BB*HH

// ---------------- scratch (device globals; no allocation allowed) ----------------
__device__ float g_q[BB * CC * NN];                       // 8 MB
__device__ float g_k[BB * CC * NN];                       // 8 MB
__device__ float g_v[BB * CC * NN];                       // 8 MB
__device__ float g_y[BB * CC * NN];                       // 8 MB
__device__ float g_attn[(size_t)BHH * NN * NN];           // 128 MB

#define FMA16(a, bv, acc)                                                        \
    do {                                                                         \
        acc[0][0] += a.x * bv.x; acc[0][1] += a.x * bv.y;                        \
        acc[0][2] += a.x * bv.z; acc[0][3] += a.x * bv.w;                        \
        acc[1][0] += a.y * bv.x; acc[1][1] += a.y * bv.y;                        \
        acc[1][2] += a.y * bv.z; acc[1][3] += a.y * bv.w;                        \
        acc[2][0] += a.z * bv.x; acc[2][1] += a.z * bv.y;                        \
        acc[2][2] += a.z * bv.z; acc[2][3] += a.z * bv.w;                        \
        acc[3][0] += a.w * bv.x; acc[3][1] += a.w * bv.y;                        \
        acc[3][2] += a.w * bv.z; acc[3][3] += a.w * bv.w;                        \
    } while (0)

// ---------------- generic 512-K channel GEMM tile: O[o,n] = sum_c W[o,c] X[c,n] --
// Block computes a 64(o) x 64(n) tile. 256 threads, 4x4 per thread.
__device__ __forceinline__ void gemm_tile_512(
    const float* __restrict__ W,   // (512,512) row-major, row = output channel
    const float* __restrict__ X,   // (512,1024) this batch
    float* __restrict__ O,         // (512,1024) this batch
    int o0, int n0)
{
    __shared__ __align__(16) float Ws[16][68];  // [k][o]
    __shared__ __align__(16) float Xs[16][68];  // [k][n]
    const int tid = threadIdx.x;
    const int tx = tid & 15;
    const int ty = tid >> 4;
    float acc[4][4] = {};

    for (int k0 = 0; k0 < CC; k0 += 16) {
        // W tile: 64 rows(o) x 16 cols(k); read float4 along k, store transposed
        {
            int oo = tid >> 2;
            int kk = (tid & 3) << 2;
            float4 w4 = *reinterpret_cast<const float4*>(W + (size_t)(o0 + oo) * CC + k0 + kk);
            Ws[kk + 0][oo] = w4.x; Ws[kk + 1][oo] = w4.y;
            Ws[kk + 2][oo] = w4.z; Ws[kk + 3][oo] = w4.w;
        }
        // X tile: 16 rows(k) x 64 cols(n); fully coalesced
        {
            int kk = tid >> 4;
            int nn = (tid & 15) << 2;
            *reinterpret_cast<float4*>(&Xs[kk][nn]) =
                *reinterpret_cast<const float4*>(X + (size_t)(k0 + kk) * NN + n0 + nn);
        }
        __syncthreads();
        #pragma unroll
        for (int kk = 0; kk < 16; kk++) {
            float4 a  = *reinterpret_cast<const float4*>(&Ws[kk][ty << 2]);
            float4 bv = *reinterpret_cast<const float4*>(&Xs[kk][tx << 2]);
            FMA16(a, bv, acc);
        }
        __syncthreads();
    }

    #pragma unroll
    for (int i = 0; i < 4; i++) {
        float4 r = make_float4(acc[i][0], acc[i][1], acc[i][2], acc[i][3]);
        *reinterpret_cast<float4*>(O + (size_t)(o0 + (ty << 2) + i) * NN + n0 + (tx << 2)) = r;
    }
}

// ---------------- kernel 1: fused QKV projection --------------------------------
__global__ void proj_qkv_kernel(const float* __restrict__ x,
                                const float* __restrict__ Wq,
                                const float* __restrict__ Wk,
                                const float* __restrict__ Wv)
{
    int z = blockIdx.z;
    int b = z / 3;
    int w = z - b * 3;
    const float* W = (w == 0) ? Wq : (w == 1) ? Wk : Wv;
    float* O = ((w == 0) ? g_q : (w == 1) ? g_k : g_v) + (size_t)b * CC * NN;
    gemm_tile_512(W, x + (size_t)b * CC * NN, O, blockIdx.y << 6, blockIdx.x << 6);
}

// ---------------- kernel 2: scores[bh,i,j] = sum_d q[d,i] k[d,j] -----------------
__global__ void scores_kernel()
{
    const int bh = blockIdx.z;
    const int b = bh >> 3, h = bh & 7;
    const float* qh = g_q + ((size_t)b * CC + (size_t)h * DD) * NN;
    const float* kh = g_k + ((size_t)b * CC + (size_t)h * DD) * NN;
    const int i0 = blockIdx.y << 6;
    const int j0 = blockIdx.x << 6;

    __shared__ __align__(16) float Qs[64][68];  // [d][i]
    __shared__ __align__(16) float Ks[64][68];  // [d][j]
    const int tid = threadIdx.x;
    const int tx = tid & 15;
    const int ty = tid >> 4;

    #pragma unroll
    for (int r = 0; r < 4; r++) {
        int d = (tid >> 4) + r * 16;
        int c = (tid & 15) << 2;
        *reinterpret_cast<float4*>(&Qs[d][c]) =
            *reinterpret_cast<const float4*>(qh + (size_t)d * NN + i0 + c);
        *reinterpret_cast<float4*>(&Ks[d][c]) =
            *reinterpret_cast<const float4*>(kh + (size_t)d * NN + j0 + c);
    }
    __syncthreads();

    float acc[4][4] = {};
    #pragma unroll 16
    for (int d = 0; d < 64; d++) {
        float4 a  = *reinterpret_cast<const float4*>(&Qs[d][ty << 2]);
        float4 bv = *reinterpret_cast<const float4*>(&Ks[d][tx << 2]);
        FMA16(a, bv, acc);
    }

    float* ap = g_attn + (size_t)bh * NN * NN;
    #pragma unroll
    for (int i = 0; i < 4; i++) {
        float4 r = make_float4(acc[i][0], acc[i][1], acc[i][2], acc[i][3]);
        *reinterpret_cast<float4*>(ap + (size_t)(i0 + (ty << 2) + i) * NN + j0 + (tx << 2)) = r;
    }
}

// ---------------- kernel 3: row softmax over j (in place) -----------------------
__global__ void softmax_kernel()
{
    float* p = g_attn + (size_t)blockIdx.x * NN;
    const int tid = threadIdx.x;
    float4 v = *reinterpret_cast<const float4*>(p + (tid << 2));

    __shared__ float red_max[8];
    __shared__ float red_sum[8];

    float m = fmaxf(fmaxf(v.x, v.y), fmaxf(v.z, v.w));
    #pragma unroll
    for (int o = 16; o > 0; o >>= 1) m = fmaxf(m, __shfl_xor_sync(0xffffffffu, m, o));
    if ((tid & 31) == 0) red_max[tid >> 5] = m;
    __syncthreads();
    float M = red_max[0];
    #pragma unroll
    for (int i = 1; i < 8; i++) M = fmaxf(M, red_max[i]);

    float e0 = __expf(v.x - M);
    float e1 = __expf(v.y - M);
    float e2 = __expf(v.z - M);
    float e3 = __expf(v.w - M);
    float s = (e0 + e1) + (e2 + e3);
    #pragma unroll
    for (int o = 16; o > 0; o >>= 1) s += __shfl_xor_sync(0xffffffffu, s, o);
    if ((tid & 31) == 0) red_sum[tid >> 5] = s;
    __syncthreads();
    float S = 0.f;
    #pragma unroll
    for (int i = 0; i < 8; i++) S += red_sum[i];
    float inv = 1.0f / S;

    *reinterpret_cast<float4*>(p + (tid << 2)) =
        make_float4(e0 * inv, e1 * inv, e2 * inv, e3 * inv);
}

// ---------------- kernel 4: y[d,i] = sum_j attn[i,j] v[d,j] ---------------------
__global__ void attn_v_kernel()
{
    const int bh = blockIdx.z;
    const int b = bh >> 3, h = bh & 7;
    const float* vh = g_v + ((size_t)b * CC + (size_t)h * DD) * NN;
    const float* ah = g_attn + (size_t)bh * NN * NN;
    float*       yh = g_y + ((size_t)b * CC + (size_t)h * DD) * NN;
    const int i0 = blockIdx.x << 6;

    __shared__ __align__(16) float Vs[64][68];  // [j][d] (transposed)
    __shared__ __align__(16) float As[64][68];  // [j][i] (transposed)
    const int tid = threadIdx.x;
    const int tx = tid & 15;
    const int ty = tid >> 4;

    float acc[4][4] = {};  // acc[d][i]
    for (int j0 = 0; j0 < NN; j0 += 64) {
        #pragma unroll
        for (int r = 0; r < 4; r++) {
            int a_ = (tid >> 4) + r * 16;     // d index for V; i index for A
            int jj = (tid & 15) << 2;
            float4 vv = *reinterpret_cast<const float4*>(vh + (size_t)a_ * NN + j0 + jj);
            Vs[jj + 0][a_] = vv.x; Vs[jj + 1][a_] = vv.y;
            Vs[jj + 2][a_] = vv.z; Vs[jj + 3][a_] = vv.w;
            float4 av = *reinterpret_cast<const float4*>(ah + (size_t)(i0 + a_) * NN + j0 + jj);
            As[jj + 0][a_] = av.x; As[jj + 1][a_] = av.y;
            As[jj + 2][a_] = av.z; As[jj + 3][a_] = av.w;
        }
        __syncthreads();
        #pragma unroll 16
        for (int j = 0; j < 64; j++) {
            float4 a  = *reinterpret_cast<const float4*>(&Vs[j][ty << 2]);  // 4 d's
            float4 bv = *reinterpret_cast<const float4*>(&As[j][tx << 2]);  // 4 i's
            FMA16(a, bv, acc);
        }
        __syncthreads();
    }

    #pragma unroll
    for (int r = 0; r < 4; r++) {
        float4 out = make_float4(acc[r][0], acc[r][1], acc[r][2], acc[r][3]);
        *reinterpret_cast<float4*>(yh + (size_t)((ty << 2) + r) * NN + i0 + (tx << 2)) = out;
    }
}

// ---------------- kernel 5: out = Wo @ y -----------------------------------------
__global__ void proj_out_kernel(const float* __restrict__ Wo, float* __restrict__ out)
{
    int b = blockIdx.z;
    gemm_tile_512(Wo, g_y + (size_t)b * CC * NN, out + (size_t)b * CC * NN,
                  blockIdx.y << 6, blockIdx.x << 6);
}

// ---------------- entry ----------------------------------------------------------
extern "C" void kernel_launch(void* const* d_in, const int* in_sizes, int n_in,
                              void* d_out, int out_size)
{
    const float* x  = (const float*)d_in[0];
    const float* Wq = (const float*)d_in[1];
    const float* Wk = (const float*)d_in[2];
    const float* Wv = (const float*)d_in[3];
    const float* Wo = (const float*)d_in[4];
    float* out = (float*)d_out;

    dim3 blk(256);
    proj_qkv_kernel<<<dim3(NN / 64, CC / 64, BB * 3), blk>>>(x, Wq, Wk, Wv);
    scores_kernel  <<<dim3(NN / 64, NN / 64, BHH), blk>>>();
    softmax_kernel <<<dim3(BHH * NN), blk>>>();
    attn_v_kernel  <<<dim3(NN / 64, 1, BHH), blk>>>();
    proj_out_kernel<<<dim3(NN / 64, CC / 64, BB), blk>>>(Wo, out);
}

// round 2
// speedup vs baseline: 1.0037x; 1.0037x over previous
#include <cuda_runtime.h>
#include <cstdint>

// Problem constants
#define BB   4
#define CC   512
#define NN   1024
#define HH   8
#define DD   64
#define BHH  32   // BB*HH

// ---------------- scratch (device globals; no allocation allowed) ----------------
__device__ float g_q[BB * CC * NN];                       // 8 MB
__device__ float g_k[BB * CC * NN];                       // 8 MB
__device__ float g_v[BB * CC * NN];                       // 8 MB
__device__ float g_y[BB * CC * NN];                       // 8 MB
__device__ float g_attn[(size_t)BHH * NN * NN];           // 128 MB

#define FMA16(a, bv, acc)                                                        \
    do {                                                                         \
        acc[0][0] += a.x * bv.x; acc[0][1] += a.x * bv.y;                        \
        acc[0][2] += a.x * bv.z; acc[0][3] += a.x * bv.w;                        \
        acc[1][0] += a.y * bv.x; acc[1][1] += a.y * bv.y;                        \
        acc[1][2] += a.y * bv.z; acc[1][3] += a.y * bv.w;                        \
        acc[2][0] += a.z * bv.x; acc[2][1] += a.z * bv.y;                        \
        acc[2][2] += a.z * bv.z; acc[2][3] += a.z * bv.w;                        \
        acc[3][0] += a.w * bv.x; acc[3][1] += a.w * bv.y;                        \
        acc[3][2] += a.w * bv.z; acc[3][3] += a.w * bv.w;                        \
    } while (0)

// ---------------- generic 512-K channel GEMM tile: O[o,n] = sum_c W[o,c] X[c,n] --
// Block computes a 64(o) x 64(n) tile. 256 threads, 4x4 per thread.
__device__ __forceinline__ void gemm_tile_512(
    const float* __restrict__ W,   // (512,512) row-major, row = output channel
    const float* __restrict__ X,   // (512,1024) this batch
    float* __restrict__ O,         // (512,1024) this batch
    int o0, int n0)
{
    __shared__ __align__(16) float Ws[16][68];  // [k][o]
    __shared__ __align__(16) float Xs[16][68];  // [k][n]
    const int tid = threadIdx.x;
    const int tx = tid & 15;
    const int ty = tid >> 4;
    float acc[4][4] = {};

    for (int k0 = 0; k0 < CC; k0 += 16) {
        // W tile: 64 rows(o) x 16 cols(k); read float4 along k, store transposed
        {
            int oo = tid >> 2;
            int kk = (tid & 3) << 2;
            float4 w4 = *reinterpret_cast<const float4*>(W + (size_t)(o0 + oo) * CC + k0 + kk);
            Ws[kk + 0][oo] = w4.x; Ws[kk + 1][oo] = w4.y;
            Ws[kk + 2][oo] = w4.z; Ws[kk + 3][oo] = w4.w;
        }
        // X tile: 16 rows(k) x 64 cols(n); fully coalesced
        {
            int kk = tid >> 4;
            int nn = (tid & 15) << 2;
            *reinterpret_cast<float4*>(&Xs[kk][nn]) =
                *reinterpret_cast<const float4*>(X + (size_t)(k0 + kk) * NN + n0 + nn);
        }
        __syncthreads();
        #pragma unroll
        for (int kk = 0; kk < 16; kk++) {
            float4 a  = *reinterpret_cast<const float4*>(&Ws[kk][ty << 2]);
            float4 bv = *reinterpret_cast<const float4*>(&Xs[kk][tx << 2]);
            FMA16(a, bv, acc);
        }
        __syncthreads();
    }

    #pragma unroll
    for (int i = 0; i < 4; i++) {
        float4 r = make_float4(acc[i][0], acc[i][1], acc[i][2], acc[i][3]);
        *reinterpret_cast<float4*>(O + (size_t)(o0 + (ty << 2) + i) * NN + n0 + (tx << 2)) = r;
    }
}

// ---------------- kernel 1: fused QKV projection --------------------------------
__global__ void proj_qkv_kernel(const float* __restrict__ x,
                                const float* __restrict__ Wq,
                                const float* __restrict__ Wk,
                                const float* __restrict__ Wv)
{
    int z = blockIdx.z;
    int b = z / 3;
    int w = z - b * 3;
    const float* W = (w == 0) ? Wq : (w == 1) ? Wk : Wv;
    float* O = ((w == 0) ? g_q : (w == 1) ? g_k : g_v) + (size_t)b * CC * NN;
    gemm_tile_512(W, x + (size_t)b * CC * NN, O, blockIdx.y << 6, blockIdx.x << 6);
}

// ---------------- kernel 2: scores[bh,i,j] = sum_d q[d,i] k[d,j] -----------------
__global__ void scores_kernel()
{
    const int bh = blockIdx.z;
    const int b = bh >> 3, h = bh & 7;
    const float* qh = g_q + ((size_t)b * CC + (size_t)h * DD) * NN;
    const float* kh = g_k + ((size_t)b * CC + (size_t)h * DD) * NN;
    const int i0 = blockIdx.y << 6;
    const int j0 = blockIdx.x << 6;

    __shared__ __align__(16) float Qs[64][68];  // [d][i]
    __shared__ __align__(16) float Ks[64][68];  // [d][j]
    const int tid = threadIdx.x;
    const int tx = tid & 15;
    const int ty = tid >> 4;

    #pragma unroll
    for (int r = 0; r < 4; r++) {
        int d = (tid >> 4) + r * 16;
        int c = (tid & 15) << 2;
        *reinterpret_cast<float4*>(&Qs[d][c]) =
            *reinterpret_cast<const float4*>(qh + (size_t)d * NN + i0 + c);
        *reinterpret_cast<float4*>(&Ks[d][c]) =
            *reinterpret_cast<const float4*>(kh + (size_t)d * NN + j0 + c);
    }
    __syncthreads();

    float acc[4][4] = {};
    #pragma unroll 16
    for (int d = 0; d < 64; d++) {
        float4 a  = *reinterpret_cast<const float4*>(&Qs[d][ty << 2]);
        float4 bv = *reinterpret_cast<const float4*>(&Ks[d][tx << 2]);
        FMA16(a, bv, acc);
    }

    float* ap = g_attn + (size_t)bh * NN * NN;
    #pragma unroll
    for (int i = 0; i < 4; i++) {
        float4 r = make_float4(acc[i][0], acc[i][1], acc[i][2], acc[i][3]);
        *reinterpret_cast<float4*>(ap + (size_t)(i0 + (ty << 2) + i) * NN + j0 + (tx << 2)) = r;
    }
}

// ---------------- kernel 3: row softmax over j (in place) -----------------------
__global__ void softmax_kernel()
{
    float* p = g_attn + (size_t)blockIdx.x * NN;
    const int tid = threadIdx.x;
    float4 v = *reinterpret_cast<const float4*>(p + (tid << 2));

    __shared__ float red_max[8];
    __shared__ float red_sum[8];

    float m = fmaxf(fmaxf(v.x, v.y), fmaxf(v.z, v.w));
    #pragma unroll
    for (int o = 16; o > 0; o >>= 1) m = fmaxf(m, __shfl_xor_sync(0xffffffffu, m, o));
    if ((tid & 31) == 0) red_max[tid >> 5] = m;
    __syncthreads();
    float M = red_max[0];
    #pragma unroll
    for (int i = 1; i < 8; i++) M = fmaxf(M, red_max[i]);

    float e0 = __expf(v.x - M);
    float e1 = __expf(v.y - M);
    float e2 = __expf(v.z - M);
    float e3 = __expf(v.w - M);
    float s = (e0 + e1) + (e2 + e3);
    #pragma unroll
    for (int o = 16; o > 0; o >>= 1) s += __shfl_xor_sync(0xffffffffu, s, o);
    if ((tid & 31) == 0) red_sum[tid >> 5] = s;
    __syncthreads();
    float S = 0.f;
    #pragma unroll
    for (int i = 0; i < 8; i++) S += red_sum[i];
    float inv = 1.0f / S;

    *reinterpret_cast<float4*>(p + (tid << 2)) =
        make_float4(e0 * inv, e1 * inv, e2 * inv, e3 * inv);
}

// ---------------- kernel 4: y[d,i] = sum_j attn[i,j] v[d,j] ---------------------
__global__ void attn_v_kernel()
{
    const int bh = blockIdx.z;
    const int b = bh >> 3, h = bh & 7;
    const float* vh = g_v + ((size_t)b * CC + (size_t)h * DD) * NN;
    const float* ah = g_attn + (size_t)bh * NN * NN;
    float*       yh = g_y + ((size_t)b * CC + (size_t)h * DD) * NN;
    const int i0 = blockIdx.x << 6;

    __shared__ __align__(16) float Vs[64][68];  // [j][d] (transposed)
    __shared__ __align__(16) float As[64][68];  // [j][i] (transposed)
    const int tid = threadIdx.x;
    const int tx = tid & 15;
    const int ty = tid >> 4;

    float acc[4][4] = {};  // acc[d][i]
    for (int j0 = 0; j0 < NN; j0 += 64) {
        #pragma unroll
        for (int r = 0; r < 4; r++) {
            int a_ = (tid >> 4) + r * 16;     // d index for V; i index for A
            int jj = (tid & 15) << 2;
            float4 vv = *reinterpret_cast<const float4*>(vh + (size_t)a_ * NN + j0 + jj);
            Vs[jj + 0][a_] = vv.x; Vs[jj + 1][a_] = vv.y;
            Vs[jj + 2][a_] = vv.z; Vs[jj + 3][a_] = vv.w;
            float4 av = *reinterpret_cast<const float4*>(ah + (size_t)(i0 + a_) * NN + j0 + jj);
            As[jj + 0][a_] = av.x; As[jj + 1][a_] = av.y;
            As[jj + 2][a_] = av.z; As[jj + 3][a_] = av.w;
        }
        __syncthreads();
        #pragma unroll 16
        for (int j = 0; j < 64; j++) {
            float4 a  = *reinterpret_cast<const float4*>(&Vs[j][ty << 2]);  // 4 d's
            float4 bv = *reinterpret_cast<const float4*>(&As[j][tx << 2]);  // 4 i's
            FMA16(a, bv, acc);
        }
        __syncthreads();
    }

    #pragma unroll
    for (int r = 0; r < 4; r++) {
        float4 out = make_float4(acc[r][0], acc[r][1], acc[r][2], acc[r][3]);
        *reinterpret_cast<float4*>(yh + (size_t)((ty << 2) + r) * NN + i0 + (tx << 2)) = out;
    }
}

// ---------------- kernel 5: out = Wo @ y -----------------------------------------
__global__ void proj_out_kernel(const float* __restrict__ Wo, float* __restrict__ out)
{
    int b = blockIdx.z;
    gemm_tile_512(Wo, g_y + (size_t)b * CC * NN, out + (size_t)b * CC * NN,
                  blockIdx.y << 6, blockIdx.x << 6);
}

// ---------------- entry ----------------------------------------------------------
extern "C" void kernel_launch(void* const* d_in, const int* in_sizes, int n_in,
                              void* d_out, int out_size)
{
    const float* x  = (const float*)d_in[0];
    const float* Wq = (const float*)d_in[1];
    const float* Wk = (const float*)d_in[2];
    const float* Wv = (const float*)d_in[3];
    const float* Wo = (const float*)d_in[4];
    float* out = (float*)d_out;

    dim3 blk(256);
    proj_qkv_kernel<<<dim3(NN / 64, CC / 64, BB * 3), blk>>>(x, Wq, Wk, Wv);
    scores_kernel  <<<dim3(NN / 64, NN / 64, BHH), blk>>>();
    softmax_kernel <<<dim3(BHH * NN), blk>>>();
    attn_v_kernel  <<<dim3(NN / 64, 1, BHH), blk>>>();
    proj_out_kernel<<<dim3(NN / 64, CC / 64, BB), blk>>>(Wo, out);
}

// round 4
// speedup vs baseline: 2.3163x; 2.3079x over previous
#include <cuda_runtime.h>
#include <cuda_bf16.h>
#include <cstdint>

#define BB 4
#define CC 512
#define NN 1024
#define HH 8
#define DD 64
#define BHH 32

// ---------------- bf16 hi/lo split scratch (device globals) ----------------
__device__ __nv_bfloat16 g_xh[BB * NN * CC], g_xl[BB * NN * CC];   // xT [b][n][c]
__device__ __nv_bfloat16 g_wh[4 * CC * CC],  g_wl[4 * CC * CC];    // Wq,Wk,Wv,Wo [o][c]
__device__ __nv_bfloat16 g_qh[BHH * NN * DD], g_ql[BHH * NN * DD]; // [bh][i][d]
__device__ __nv_bfloat16 g_kh[BHH * NN * DD], g_kl[BHH * NN * DD]; // [bh][j][d]
__device__ __nv_bfloat16 g_vh[BB * CC * NN],  g_vl[BB * CC * NN];  // [b][o][n] = [bh][d][j]
__device__ __nv_bfloat16 g_yh[BB * NN * CC],  g_yl[BB * NN * CC];  // yT [b][i][c]

// ================= helpers =================
__device__ __forceinline__ uint32_t smem_u32(const void* p) {
    uint32_t a;
    asm("{ .reg .u64 t; cvta.to.shared.u64 t, %1; cvt.u32.u64 %0, t; }" : "=r"(a) : "l"(p));
    return a;
}
__device__ __forceinline__ void cp16(uint32_t dst, const void* src) {
    asm volatile("cp.async.cg.shared.global [%0], [%1], 16;" :: "r"(dst), "l"(src));
}
__device__ __forceinline__ void cp_wait_all() {
    asm volatile("cp.async.commit_group;");
    asm volatile("cp.async.wait_group 0;");
}
__device__ __forceinline__ void ldmx4(uint32_t r[4], uint32_t addr) {
    asm volatile("ldmatrix.sync.aligned.m8n8.x4.shared.b16 {%0,%1,%2,%3}, [%4];"
                 : "=r"(r[0]), "=r"(r[1]), "=r"(r[2]), "=r"(r[3]) : "r"(addr));
}
__device__ __forceinline__ void mma16816(float c[4], const uint32_t a[4], uint32_t b0, uint32_t b1) {
    asm volatile(
        "mma.sync.aligned.m16n8k16.row.col.f32.bf16.bf16.f32 "
        "{%0,%1,%2,%3}, {%4,%5,%6,%7}, {%8,%9}, {%0,%1,%2,%3};"
        : "+f"(c[0]), "+f"(c[1]), "+f"(c[2]), "+f"(c[3])
        : "r"(a[0]), "r"(a[1]), "r"(a[2]), "r"(a[3]), "r"(b0), "r"(b1));
}
// ldmatrix source address: 8x8 sub-matrix pattern for A-style 16x16 tiles.
// thread t: m=t>>3 (matrix id), row=(m&1)*8 + (t&7), k=(m>>1)*8
__device__ __forceinline__ uint32_t frag_addr(uint32_t base, int row0, int k0, int pitchB) {
    int lane = threadIdx.x & 31;
    int m = lane >> 3, r = lane & 7;
    int row = row0 + ((m & 1) << 3) + r;
    int k = k0 + ((m >> 1) << 3);
    return base + (uint32_t)(row * pitchB + k * 2);
}
__device__ __forceinline__ void split_pack(float a, float b, uint32_t& hi, uint32_t& lo) {
    __nv_bfloat16 ha = __float2bfloat16(a), hb = __float2bfloat16(b);
    __nv_bfloat16 la = __float2bfloat16(a - __bfloat162float(ha));
    __nv_bfloat16 lb = __float2bfloat16(b - __bfloat162float(hb));
    hi = (uint32_t)__bfloat16_as_ushort(ha) | ((uint32_t)__bfloat16_as_ushort(hb) << 16);
    lo = (uint32_t)__bfloat16_as_ushort(la) | ((uint32_t)__bfloat16_as_ushort(lb) << 16);
}

// ---------------- prep: split weights ----------------
__global__ __launch_bounds__(256) void prep_w_kernel(const float* __restrict__ Wq,
                                                     const float* __restrict__ Wk,
                                                     const float* __restrict__ Wv,
                                                     const float* __restrict__ Wo)
{
    int w = blockIdx.y;
    const float* W = (w == 0) ? Wq : (w == 1) ? Wk : (w == 2) ? Wv : Wo;
    int i = (blockIdx.x * 256 + threadIdx.x) * 4;
    float4 v = *(const float4*)(W + i);
    uint32_t h0, l0, h1, l1;
    split_pack(v.x, v.y, h0, l0);
    split_pack(v.z, v.w, h1, l1);
    size_t o = (size_t)w * CC * CC + i;
    *(uint2*)(g_wh + o) = make_uint2(h0, h1);
    *(uint2*)(g_wl + o) = make_uint2(l0, l1);
}

// ---------------- prep: transpose + split x -> xT ----------------
__global__ void prep_x_kernel(const float* __restrict__ x)
{
    __shared__ float t[32][33];
    int b = blockIdx.z;
    int n0 = blockIdx.x << 5, c0 = blockIdx.y << 5;
    int tx = threadIdx.x, ty = threadIdx.y;
    #pragma unroll
    for (int k = 0; k < 4; k++)
        t[ty + k * 8][tx] = x[((size_t)b * CC + c0 + ty + k * 8) * NN + n0 + tx];
    __syncthreads();
    #pragma unroll
    for (int k = 0; k < 4; k++) {
        int n = n0 + ty + k * 8;
        float v = t[tx][ty + k * 8];
        __nv_bfloat16 h = __float2bfloat16(v);
        __nv_bfloat16 l = __float2bfloat16(v - __bfloat162float(h));
        size_t idx = ((size_t)b * NN + n) * CC + c0 + tx;
        g_xh[idx] = h;
        g_xl[idx] = l;
    }
}

// ---------------- proj QKV: D[o,n] = W[o,:].xT[n,:]  (3xBF16) --------------------
// Block: 256 thr (8 warps, 4Mx2N), tile M=128(o) x N=128(n), K=512 in chunks of 32.
#define P_AH 0u
#define P_AL 10240u
#define P_BH 20480u
#define P_BL 30720u
#define PROJ_SMEM 67584   // max(40960 mainloop, 128*132*4 epilogue)

__global__ __launch_bounds__(256) void proj_qkv_kernel()
{
    extern __shared__ char sm[];
    const int tid = threadIdx.x, lane = tid & 31, wid = tid >> 5;
    const int wm = wid & 3, wn = wid >> 2;
    const int z = blockIdx.z, b = z / 3, mtx = z - b * 3;  // 0=q 1=k 2=v
    const int o0 = blockIdx.y << 7, n0 = blockIdx.x << 7;
    const __nv_bfloat16* Ah = g_wh + (size_t)mtx * CC * CC;
    const __nv_bfloat16* Al = g_wl + (size_t)mtx * CC * CC;
    const __nv_bfloat16* Bh = g_xh + (size_t)b * NN * CC;
    const __nv_bfloat16* Bl = g_xl + (size_t)b * NN * CC;
    const uint32_t sb = smem_u32(sm);

    float c[2][8][4] = {};
    for (int k0 = 0; k0 < CC; k0 += 32) {
        #pragma unroll
        for (int t = tid; t < 512; t += 256) {
            int r = t >> 2, ch = t & 3;
            uint32_t d = (uint32_t)(r * 80 + ch * 16);
            size_t sA = (size_t)(o0 + r) * CC + k0 + ch * 8;
            size_t sB = (size_t)(n0 + r) * CC + k0 + ch * 8;
            cp16(sb + P_AH + d, Ah + sA);
            cp16(sb + P_AL + d, Al + sA);
            cp16(sb + P_BH + d, Bh + sB);
            cp16(sb + P_BL + d, Bl + sB);
        }
        cp_wait_all();
        __syncthreads();
        #pragma unroll
        for (int ks = 0; ks < 2; ks++) {
            uint32_t ah[2][4], al[2][4], bhv[8][2], blv[8][2];
            ldmx4(ah[0], frag_addr(sb + P_AH, wm * 32,      ks * 16, 80));
            ldmx4(ah[1], frag_addr(sb + P_AH, wm * 32 + 16, ks * 16, 80));
            ldmx4(al[0], frag_addr(sb + P_AL, wm * 32,      ks * 16, 80));
            ldmx4(al[1], frag_addr(sb + P_AL, wm * 32 + 16, ks * 16, 80));
            #pragma unroll
            for (int g = 0; g < 4; g++) {
                uint32_t r4[4];
                ldmx4(r4, frag_addr(sb + P_BH, wn * 64 + g * 16, ks * 16, 80));
                bhv[2*g][0] = r4[0]; bhv[2*g][1] = r4[2];
                bhv[2*g+1][0] = r4[1]; bhv[2*g+1][1] = r4[3];
                ldmx4(r4, frag_addr(sb + P_BL, wn * 64 + g * 16, ks * 16, 80));
                blv[2*g][0] = r4[0]; blv[2*g][1] = r4[2];
                blv[2*g+1][0] = r4[1]; blv[2*g+1][1] = r4[3];
            }
            #pragma unroll
            for (int mf = 0; mf < 2; mf++)
                #pragma unroll
                for (int nf = 0; nf < 8; nf++) {
                    mma16816(c[mf][nf], ah[mf], bhv[nf][0], bhv[nf][1]);
                    mma16816(c[mf][nf], ah[mf], blv[nf][0], blv[nf][1]);
                    mma16816(c[mf][nf], al[mf], bhv[nf][0], bhv[nf][1]);
                }
        }
        __syncthreads();
    }

    if (mtx == 2) {
        // v: split store [b][o][n]
        #pragma unroll
        for (int mf = 0; mf < 2; mf++)
            #pragma unroll
            for (int nf = 0; nf < 8; nf++) {
                int row = o0 + wm * 32 + mf * 16 + (lane >> 2);
                int col = n0 + wn * 64 + nf * 8 + ((lane & 3) << 1);
                uint32_t hi, lo;
                split_pack(c[mf][nf][0], c[mf][nf][1], hi, lo);
                size_t idx = (size_t)(b * CC + row) * NN + col;
                *(uint32_t*)(g_vh + idx) = hi;
                *(uint32_t*)(g_vl + idx) = lo;
                split_pack(c[mf][nf][2], c[mf][nf][3], hi, lo);
                idx = (size_t)(b * CC + row + 8) * NN + col;
                *(uint32_t*)(g_vh + idx) = hi;
                *(uint32_t*)(g_vl + idx) = lo;
            }
    } else {
        // q/k: transpose via smem, split store [bh][i][d]
        float* ep = (float*)sm;
        #pragma unroll
        for (int mf = 0; mf < 2; mf++)
            #pragma unroll
            for (int nf = 0; nf < 8; nf++) {
                int ro = wm * 32 + mf * 16 + (lane >> 2);
                int cn = wn * 64 + nf * 8 + ((lane & 3) << 1);
                ep[cn * 132 + ro]           = c[mf][nf][0];
                ep[(cn + 1) * 132 + ro]     = c[mf][nf][1];
                ep[cn * 132 + ro + 8]       = c[mf][nf][2];
                ep[(cn + 1) * 132 + ro + 8] = c[mf][nf][3];
            }
        __syncthreads();
        __nv_bfloat16* oh = (mtx == 0) ? g_qh : g_kh;
        __nv_bfloat16* ol = (mtx == 0) ? g_ql : g_kl;
        int n = tid >> 1, half = tid & 1;
        int h = (o0 >> 6) + half;
        size_t base = ((size_t)(b * HH + h) * NN + n0 + n) * DD;
        #pragma unroll
        for (int d = 0; d < 64; d += 2) {
            float v0 = ep[n * 132 + half * 64 + d];
            float v1 = ep[n * 132 + half * 64 + d + 1];
            uint32_t hi, lo;
            split_pack(v0, v1, hi, lo);
            *(uint32_t*)(oh + base + d) = hi;
            *(uint32_t*)(ol + base + d) = lo;
        }
    }
}

// ---------------- fused attention ------------------------------------------------
// Block 256 thr (8 warps). Per (bh, 128-row i-tile). j loop over 8 blocks of 128.
#define A_QH 0u
#define A_QL 18432u
#define A_KH 36864u
#define A_KL 55296u
#define A_VH 73728u
#define A_VL 91136u
#define A_PH 108544u
#define A_PL 143360u
#define A_RS 178176u
#define ATTN_SMEM 179200

__global__ __launch_bounds__(256) void attn_kernel()
{
    extern __shared__ char sm[];
    const int tid = threadIdx.x, lane = tid & 31, wid = tid >> 5;
    const int wm = wid & 3, wn = wid >> 2;
    const int bh = blockIdx.y, b = bh >> 3, h = bh & 7;
    const int i0 = blockIdx.x << 7;
    const uint32_t sb = smem_u32(sm);

    // Q tile load (once): [128 i][64 d] hi/lo
    #pragma unroll
    for (int t = tid; t < 1024; t += 256) {
        int r = t >> 3, ch = t & 7;
        uint32_t d = (uint32_t)(r * 144 + ch * 16);
        size_t s = ((size_t)bh * NN + i0 + r) * DD + ch * 8;
        cp16(sb + A_QH + d, g_qh + s);
        cp16(sb + A_QL + d, g_ql + s);
    }

    float yc[2][4][4] = {};
    float rs[4] = {0.f, 0.f, 0.f, 0.f};

    for (int jb = 0; jb < 8; jb++) {
        int j0 = jb * 128;
        // K tile [128 j][64 d], V tile [64 d][128 j]
        #pragma unroll
        for (int t = tid; t < 1024; t += 256) {
            int r = t >> 3, ch = t & 7;
            uint32_t d = (uint32_t)(r * 144 + ch * 16);
            size_t s = ((size_t)bh * NN + j0 + r) * DD + ch * 8;
            cp16(sb + A_KH + d, g_kh + s);
            cp16(sb + A_KL + d, g_kl + s);
        }
        #pragma unroll
        for (int t = tid; t < 1024; t += 256) {
            int r = t >> 4, ch = t & 15;
            uint32_t d = (uint32_t)(r * 272 + ch * 16);
            size_t s = (size_t)(b * CC + h * DD + r) * NN + j0 + ch * 8;
            cp16(sb + A_VH + d, g_vh + s);
            cp16(sb + A_VL + d, g_vl + s);
        }
        cp_wait_all();
        __syncthreads();

        // S = Q.K^T  (3xBF16), warp tile 32(i) x 64(j)
        float cs[2][8][4] = {};
        #pragma unroll
        for (int ks = 0; ks < 4; ks++) {
            uint32_t ah[2][4], al[2][4], bhv[8][2], blv[8][2];
            ldmx4(ah[0], frag_addr(sb + A_QH, wm * 32,      ks * 16, 144));
            ldmx4(ah[1], frag_addr(sb + A_QH, wm * 32 + 16, ks * 16, 144));
            ldmx4(al[0], frag_addr(sb + A_QL, wm * 32,      ks * 16, 144));
            ldmx4(al[1], frag_addr(sb + A_QL, wm * 32 + 16, ks * 16, 144));
            #pragma unroll
            for (int g = 0; g < 4; g++) {
                uint32_t r4[4];
                ldmx4(r4, frag_addr(sb + A_KH, wn * 64 + g * 16, ks * 16, 144));
                bhv[2*g][0] = r4[0]; bhv[2*g][1] = r4[2];
                bhv[2*g+1][0] = r4[1]; bhv[2*g+1][1] = r4[3];
                ldmx4(r4, frag_addr(sb + A_KL, wn * 64 + g * 16, ks * 16, 144));
                blv[2*g][0] = r4[0]; blv[2*g][1] = r4[2];
                blv[2*g+1][0] = r4[1]; blv[2*g+1][1] = r4[3];
            }
            #pragma unroll
            for (int mf = 0; mf < 2; mf++)
                #pragma unroll
                for (int nf = 0; nf < 8; nf++) {
                    mma16816(cs[mf][nf], ah[mf], bhv[nf][0], bhv[nf][1]);
                    mma16816(cs[mf][nf], ah[mf], blv[nf][0], blv[nf][1]);
                    mma16816(cs[mf][nf], al[mf], bhv[nf][0], bhv[nf][1]);
                }
        }

        // exp (unnormalized), accumulate rowsum, split P -> smem
        #pragma unroll
        for (int mf = 0; mf < 2; mf++)
            #pragma unroll
            for (int nf = 0; nf < 8; nf++) {
                int prow = wm * 32 + mf * 16 + (lane >> 2);
                int pcol = wn * 64 + nf * 8 + ((lane & 3) << 1);
                float p0 = __expf(cs[mf][nf][0]);
                float p1 = __expf(cs[mf][nf][1]);
                float p2 = __expf(cs[mf][nf][2]);
                float p3 = __expf(cs[mf][nf][3]);
                rs[mf * 2 + 0] += p0 + p1;
                rs[mf * 2 + 1] += p2 + p3;
                uint32_t hi, lo;
                split_pack(p0, p1, hi, lo);
                *(uint32_t*)(sm + A_PH + prow * 272 + pcol * 2) = hi;
                *(uint32_t*)(sm + A_PL + prow * 272 + pcol * 2) = lo;
                split_pack(p2, p3, hi, lo);
                *(uint32_t*)(sm + A_PH + (prow + 8) * 272 + pcol * 2) = hi;
                *(uint32_t*)(sm + A_PL + (prow + 8) * 272 + pcol * 2) = lo;
            }
        __syncthreads();

        // Y += P.V^T  (3xBF16), warp tile 32(i) x 32(d)
        #pragma unroll
        for (int ks = 0; ks < 8; ks++) {
            uint32_t ah[2][4], al[2][4], bhv[4][2], blv[4][2];
            ldmx4(ah[0], frag_addr(sb + A_PH, wm * 32,      ks * 16, 272));
            ldmx4(ah[1], frag_addr(sb + A_PH, wm * 32 + 16, ks * 16, 272));
            ldmx4(al[0], frag_addr(sb + A_PL, wm * 32,      ks * 16, 272));
            ldmx4(al[1], frag_addr(sb + A_PL, wm * 32 + 16, ks * 16, 272));
            #pragma unroll
            for (int g = 0; g < 2; g++) {
                uint32_t r4[4];
                ldmx4(r4, frag_addr(sb + A_VH, wn * 32 + g * 16, ks * 16, 272));
                bhv[2*g][0] = r4[0]; bhv[2*g][1] = r4[2];
                bhv[2*g+1][0] = r4[1]; bhv[2*g+1][1] = r4[3];
                ldmx4(r4, frag_addr(sb + A_VL, wn * 32 + g * 16, ks * 16, 272));
                blv[2*g][0] = r4[0]; blv[2*g][1] = r4[2];
                blv[2*g+1][0] = r4[1]; blv[2*g+1][1] = r4[3];
            }
            #pragma unroll
            for (int mf = 0; mf < 2; mf++)
                #pragma unroll
                for (int nf = 0; nf < 4; nf++) {
                    mma16816(yc[mf][nf], ah[mf], bhv[nf][0], bhv[nf][1]);
                    mma16816(yc[mf][nf], ah[mf], blv[nf][0], blv[nf][1]);
                    mma16816(yc[mf][nf], al[mf], bhv[nf][0], bhv[nf][1]);
                }
        }
        __syncthreads();
    }

    // rowsum reduce: quad lanes, then across the 2 N-warps
    #pragma unroll
    for (int s = 0; s < 4; s++) {
        rs[s] += __shfl_xor_sync(0xffffffffu, rs[s], 1);
        rs[s] += __shfl_xor_sync(0xffffffffu, rs[s], 2);
    }
    float* rsm = (float*)(sm + A_RS);  // [2][128]
    if ((lane & 3) == 0) {
        #pragma unroll
        for (int s = 0; s < 4; s++) {
            int row = wm * 32 + (s >> 1) * 16 + (s & 1) * 8 + (lane >> 2);
            rsm[wn * 128 + row] = rs[s];
        }
    }
    __syncthreads();
    float inv[4];
    #pragma unroll
    for (int s = 0; s < 4; s++) {
        int row = wm * 32 + (s >> 1) * 16 + (s & 1) * 8 + (lane >> 2);
        inv[s] = 1.0f / (rsm[row] + rsm[128 + row]);
    }

    // normalize + split store yT[b][i][h*64+d]
    #pragma unroll
    for (int mf = 0; mf < 2; mf++)
        #pragma unroll
        for (int nf = 0; nf < 4; nf++) {
            int row = wm * 32 + mf * 16 + (lane >> 2);
            int d = wn * 32 + nf * 8 + ((lane & 3) << 1);
            float iv0 = inv[mf * 2 + 0], iv1 = inv[mf * 2 + 1];
            uint32_t hi, lo;
            split_pack(yc[mf][nf][0] * iv0, yc[mf][nf][1] * iv0, hi, lo);
            size_t idx = ((size_t)b * NN + i0 + row) * CC + h * DD + d;
            *(uint32_t*)(g_yh + idx) = hi;
            *(uint32_t*)(g_yl + idx) = lo;
            split_pack(yc[mf][nf][2] * iv1, yc[mf][nf][3] * iv1, hi, lo);
            idx = ((size_t)b * NN + i0 + row + 8) * CC + h * DD + d;
            *(uint32_t*)(g_yh + idx) = hi;
            *(uint32_t*)(g_yl + idx) = lo;
        }
}

// ---------------- Wo projection: out[o,n] = Wo[o,:].yT[n,:] ----------------------
__global__ __launch_bounds__(256) void proj_out_kernel(float* __restrict__ out)
{
    extern __shared__ char sm[];
    const int tid = threadIdx.x, lane = tid & 31, wid = tid >> 5;
    const int wm = wid & 3, wn = wid >> 2;
    const int b = blockIdx.z;
    const int o0 = blockIdx.y << 7, n0 = blockIdx.x << 7;
    const __nv_bfloat16* Ah = g_wh + (size_t)3 * CC * CC;
    const __nv_bfloat16* Al = g_wl + (size_t)3 * CC * CC;
    const __nv_bfloat16* Bh = g_yh + (size_t)b * NN * CC;
    const __nv_bfloat16* Bl = g_yl + (size_t)b * NN * CC;
    const uint32_t sb = smem_u32(sm);

    float c[2][8][4] = {};
    for (int k0 = 0; k0 < CC; k0 += 32) {
        #pragma unroll
        for (int t = tid; t < 512; t += 256) {
            int r = t >> 2, ch = t & 3;
            uint32_t d = (uint32_t)(r * 80 + ch * 16);
            size_t sA = (size_t)(o0 + r) * CC + k0 + ch * 8;
            size_t sB = (size_t)(n0 + r) * CC + k0 + ch * 8;
            cp16(sb + P_AH + d, Ah + sA);
            cp16(sb + P_AL + d, Al + sA);
            cp16(sb + P_BH + d, Bh + sB);
            cp16(sb + P_BL + d, Bl + sB);
        }
        cp_wait_all();
        __syncthreads();
        #pragma unroll
        for (int ks = 0; ks < 2; ks++) {
            uint32_t ah[2][4], al[2][4], bhv[8][2], blv[8][2];
            ldmx4(ah[0], frag_addr(sb + P_AH, wm * 32,      ks * 16, 80));
            ldmx4(ah[1], frag_addr(sb + P_AH, wm * 32 + 16, ks * 16, 80));
            ldmx4(al[0], frag_addr(sb + P_AL, wm * 32,      ks * 16, 80));
            ldmx4(al[1], frag_addr(sb + P_AL, wm * 32 + 16, ks * 16, 80));
            #pragma unroll
            for (int g = 0; g < 4; g++) {
                uint32_t r4[4];
                ldmx4(r4, frag_addr(sb + P_BH, wn * 64 + g * 16, ks * 16, 80));
                bhv[2*g][0] = r4[0]; bhv[2*g][1] = r4[2];
                bhv[2*g+1][0] = r4[1]; bhv[2*g+1][1] = r4[3];
                ldmx4(r4, frag_addr(sb + P_BL, wn * 64 + g * 16, ks * 16, 80));
                blv[2*g][0] = r4[0]; blv[2*g][1] = r4[2];
                blv[2*g+1][0] = r4[1]; blv[2*g+1][1] = r4[3];
            }
            #pragma unroll
            for (int mf = 0; mf < 2; mf++)
                #pragma unroll
                for (int nf = 0; nf < 8; nf++) {
                    mma16816(c[mf][nf], ah[mf], bhv[nf][0], bhv[nf][1]);
                    mma16816(c[mf][nf], ah[mf], blv[nf][0], blv[nf][1]);
                    mma16816(c[mf][nf], al[mf], bhv[nf][0], bhv[nf][1]);
                }
        }
        __syncthreads();
    }

    #pragma unroll
    for (int mf = 0; mf < 2; mf++)
        #pragma unroll
        for (int nf = 0; nf < 8; nf++) {
            int row = o0 + wm * 32 + mf * 16 + (lane >> 2);
            int col = n0 + wn * 64 + nf * 8 + ((lane & 3) << 1);
            *(float2*)(out + (size_t)(b * CC + row) * NN + col) =
                make_float2(c[mf][nf][0], c[mf][nf][1]);
            *(float2*)(out + (size_t)(b * CC + row + 8) * NN + col) =
                make_float2(c[mf][nf][2], c[mf][nf][3]);
        }
}

// ---------------- entry ----------------------------------------------------------
extern "C" void kernel_launch(void* const* d_in, const int* in_sizes, int n_in,
                              void* d_out, int out_size)
{
    const float* x  = (const float*)d_in[0];
    const float* Wq = (const float*)d_in[1];
    const float* Wk = (const float*)d_in[2];
    const float* Wv = (const float*)d_in[3];
    const float* Wo = (const float*)d_in[4];
    float* out = (float*)d_out;

    cudaFuncSetAttribute(proj_qkv_kernel, cudaFuncAttributeMaxDynamicSharedMemorySize, PROJ_SMEM);
    cudaFuncSetAttribute(proj_out_kernel, cudaFuncAttributeMaxDynamicSharedMemorySize, PROJ_SMEM);
    cudaFuncSetAttribute(attn_kernel,     cudaFuncAttributeMaxDynamicSharedMemorySize, ATTN_SMEM);

    prep_w_kernel<<<dim3(CC * CC / 1024, 4), 256>>>(Wq, Wk, Wv, Wo);
    prep_x_kernel<<<dim3(NN / 32, CC / 32, BB), dim3(32, 8)>>>(x);
    proj_qkv_kernel<<<dim3(NN / 128, CC / 128, BB * 3), 256, PROJ_SMEM>>>();
    attn_kernel<<<dim3(NN / 128, BHH), 256, ATTN_SMEM>>>();
    proj_out_kernel<<<dim3(NN / 128, CC / 128, BB), 256, PROJ_SMEM>>>(out);
}

// round 5
// speedup vs baseline: 2.5100x; 1.0836x over previous
#include <cuda_runtime.h>
#include <cuda_bf16.h>
#include <cstdint>

#define BB 4
#define CC 512
#define NN 1024
#define HH 8
#define DD 64
#define BHH 32

// ---------------- bf16 hi/lo split scratch (device globals) ----------------
__device__ __nv_bfloat16 g_xh[BB * NN * CC], g_xl[BB * NN * CC];   // xT [b][n][c]
__device__ __nv_bfloat16 g_wh[4 * CC * CC],  g_wl[4 * CC * CC];    // Wq,Wk,Wv,Wo [o][c]
__device__ __nv_bfloat16 g_qh[BHH * NN * DD], g_ql[BHH * NN * DD]; // [bh][i][d]
__device__ __nv_bfloat16 g_kh[BHH * NN * DD], g_kl[BHH * NN * DD]; // [bh][j][d]
__device__ __nv_bfloat16 g_vh[BB * CC * NN],  g_vl[BB * CC * NN];  // [b][o][n] = [bh][d][j]
__device__ __nv_bfloat16 g_yh[BB * NN * CC],  g_yl[BB * NN * CC];  // yT [b][i][c]

// ================= helpers =================
__device__ __forceinline__ uint32_t smem_u32(const void* p) {
    uint32_t a;
    asm("{ .reg .u64 t; cvta.to.shared.u64 t, %1; cvt.u32.u64 %0, t; }" : "=r"(a) : "l"(p));
    return a;
}
__device__ __forceinline__ void cp16(uint32_t dst, const void* src) {
    asm volatile("cp.async.cg.shared.global [%0], [%1], 16;" :: "r"(dst), "l"(src));
}
#define CP_COMMIT()  asm volatile("cp.async.commit_group;")
#define CP_WAIT1()   asm volatile("cp.async.wait_group 1;")
__device__ __forceinline__ void ldmx4(uint32_t r[4], uint32_t addr) {
    asm volatile("ldmatrix.sync.aligned.m8n8.x4.shared.b16 {%0,%1,%2,%3}, [%4];"
                 : "=r"(r[0]), "=r"(r[1]), "=r"(r[2]), "=r"(r[3]) : "r"(addr));
}
__device__ __forceinline__ void mma16816(float c[4], const uint32_t a[4], uint32_t b0, uint32_t b1) {
    asm volatile(
        "mma.sync.aligned.m16n8k16.row.col.f32.bf16.bf16.f32 "
        "{%0,%1,%2,%3}, {%4,%5,%6,%7}, {%8,%9}, {%0,%1,%2,%3};"
        : "+f"(c[0]), "+f"(c[1]), "+f"(c[2]), "+f"(c[3])
        : "r"(a[0]), "r"(a[1]), "r"(a[2]), "r"(a[3]), "r"(b0), "r"(b1));
}
// ldmatrix source address for 16x16 tile at (row0, k0), pitch in bytes
__device__ __forceinline__ uint32_t frag_addr(uint32_t base, int row0, int k0, int pitchB) {
    int lane = threadIdx.x & 31;
    int m = lane >> 3, r = lane & 7;
    int row = row0 + ((m & 1) << 3) + r;
    int k = k0 + ((m >> 1) << 3);
    return base + (uint32_t)(row * pitchB + k * 2);
}
__device__ __forceinline__ void split_pack(float a, float b, uint32_t& hi, uint32_t& lo) {
    __nv_bfloat16 ha = __float2bfloat16(a), hb = __float2bfloat16(b);
    __nv_bfloat16 la = __float2bfloat16(a - __bfloat162float(ha));
    __nv_bfloat16 lb = __float2bfloat16(b - __bfloat162float(hb));
    hi = (uint32_t)__bfloat16_as_ushort(ha) | ((uint32_t)__bfloat16_as_ushort(hb) << 16);
    lo = (uint32_t)__bfloat16_as_ushort(la) | ((uint32_t)__bfloat16_as_ushort(lb) << 16);
}

// ---------------- prep kernels ----------------
__global__ __launch_bounds__(256) void prep_w_kernel(const float* __restrict__ Wq,
                                                     const float* __restrict__ Wk,
                                                     const float* __restrict__ Wv,
                                                     const float* __restrict__ Wo)
{
    int w = blockIdx.y;
    const float* W = (w == 0) ? Wq : (w == 1) ? Wk : (w == 2) ? Wv : Wo;
    int i = (blockIdx.x * 256 + threadIdx.x) * 4;
    float4 v = *(const float4*)(W + i);
    uint32_t h0, l0, h1, l1;
    split_pack(v.x, v.y, h0, l0);
    split_pack(v.z, v.w, h1, l1);
    size_t o = (size_t)w * CC * CC + i;
    *(uint2*)(g_wh + o) = make_uint2(h0, h1);
    *(uint2*)(g_wl + o) = make_uint2(l0, l1);
}

__global__ void prep_x_kernel(const float* __restrict__ x)
{
    __shared__ float t[32][33];
    int b = blockIdx.z;
    int n0 = blockIdx.x << 5, c0 = blockIdx.y << 5;
    int tx = threadIdx.x, ty = threadIdx.y;
    #pragma unroll
    for (int k = 0; k < 4; k++)
        t[ty + k * 8][tx] = x[((size_t)b * CC + c0 + ty + k * 8) * NN + n0 + tx];
    __syncthreads();
    #pragma unroll
    for (int k = 0; k < 4; k++) {
        int n = n0 + ty + k * 8;
        float v = t[tx][ty + k * 8];
        __nv_bfloat16 h = __float2bfloat16(v);
        __nv_bfloat16 l = __float2bfloat16(v - __bfloat162float(h));
        size_t idx = ((size_t)b * NN + n) * CC + c0 + tx;
        g_xh[idx] = h;
        g_xl[idx] = l;
    }
}

// ---------------- shared proj mainloop: c[2][8][4] += W-tile . X-tile ------------
// 2-stage cp.async pipeline. Stage = 40960B: AH@0 AL@10240 BH@20480 BL@30720.
#define PROJ_SMEM 81920

__device__ __forceinline__ void proj_load(uint32_t st,
                                          const __nv_bfloat16* Ah, const __nv_bfloat16* Al,
                                          const __nv_bfloat16* Bh, const __nv_bfloat16* Bl,
                                          int o0, int n0, int k0)
{
    const int tid = threadIdx.x;
    #pragma unroll
    for (int t = tid; t < 512; t += 256) {
        int r = t >> 2, ch = t & 3;
        uint32_t d = (uint32_t)(r * 80 + ch * 16);
        size_t sA = (size_t)(o0 + r) * CC + k0 + ch * 8;
        size_t sB = (size_t)(n0 + r) * CC + k0 + ch * 8;
        cp16(st + 0u     + d, Ah + sA);
        cp16(st + 10240u + d, Al + sA);
        cp16(st + 20480u + d, Bh + sB);
        cp16(st + 30720u + d, Bl + sB);
    }
}

__device__ void proj_gemm(const __nv_bfloat16* Ah, const __nv_bfloat16* Al,
                          const __nv_bfloat16* Bh, const __nv_bfloat16* Bl,
                          int o0, int n0, char* sm, float c[2][8][4])
{
    const int wid = threadIdx.x >> 5;
    const int wm = wid & 3, wn = wid >> 2;
    const uint32_t sb = smem_u32(sm);

    proj_load(sb,          Ah, Al, Bh, Bl, o0, n0, 0);
    CP_COMMIT();
    proj_load(sb + 40960u, Ah, Al, Bh, Bl, o0, n0, 32);
    CP_COMMIT();

    for (int kc = 0; kc < 16; kc++) {
        uint32_t st = sb + (uint32_t)(kc & 1) * 40960u;
        CP_WAIT1();
        __syncthreads();
        #pragma unroll
        for (int ks = 0; ks < 2; ks++) {
            uint32_t ah[2][4], al[2][4], bhv[8][2], blv[8][2];
            ldmx4(ah[0], frag_addr(st + 0u,     wm * 32,      ks * 16, 80));
            ldmx4(ah[1], frag_addr(st + 0u,     wm * 32 + 16, ks * 16, 80));
            ldmx4(al[0], frag_addr(st + 10240u, wm * 32,      ks * 16, 80));
            ldmx4(al[1], frag_addr(st + 10240u, wm * 32 + 16, ks * 16, 80));
            #pragma unroll
            for (int g = 0; g < 4; g++) {
                uint32_t r4[4];
                ldmx4(r4, frag_addr(st + 20480u, wn * 64 + g * 16, ks * 16, 80));
                bhv[2*g][0] = r4[0]; bhv[2*g][1] = r4[2];
                bhv[2*g+1][0] = r4[1]; bhv[2*g+1][1] = r4[3];
                ldmx4(r4, frag_addr(st + 30720u, wn * 64 + g * 16, ks * 16, 80));
                blv[2*g][0] = r4[0]; blv[2*g][1] = r4[2];
                blv[2*g+1][0] = r4[1]; blv[2*g+1][1] = r4[3];
            }
            #pragma unroll
            for (int mf = 0; mf < 2; mf++)
                #pragma unroll
                for (int nf = 0; nf < 8; nf++) {
                    mma16816(c[mf][nf], ah[mf], bhv[nf][0], bhv[nf][1]);
                    mma16816(c[mf][nf], ah[mf], blv[nf][0], blv[nf][1]);
                    mma16816(c[mf][nf], al[mf], bhv[nf][0], bhv[nf][1]);
                }
        }
        __syncthreads();
        if (kc + 2 < 16) proj_load(st, Ah, Al, Bh, Bl, o0, n0, (kc + 2) * 32);
        CP_COMMIT();
    }
}

// ---------------- proj QKV ----------------
__global__ __launch_bounds__(256) void proj_qkv_kernel()
{
    extern __shared__ char sm[];
    const int tid = threadIdx.x, lane = tid & 31, wid = tid >> 5;
    const int wm = wid & 3, wn = wid >> 2;
    const int z = blockIdx.z, b = z / 3, mtx = z - b * 3;  // 0=q 1=k 2=v
    const int o0 = blockIdx.y << 7, n0 = blockIdx.x << 7;

    float c[2][8][4] = {};
    proj_gemm(g_wh + (size_t)mtx * CC * CC, g_wl + (size_t)mtx * CC * CC,
              g_xh + (size_t)b * NN * CC, g_xl + (size_t)b * NN * CC,
              o0, n0, sm, c);

    if (mtx == 2) {
        // v: split store [b][o][n]
        #pragma unroll
        for (int mf = 0; mf < 2; mf++)
            #pragma unroll
            for (int nf = 0; nf < 8; nf++) {
                int row = o0 + wm * 32 + mf * 16 + (lane >> 2);
                int col = n0 + wn * 64 + nf * 8 + ((lane & 3) << 1);
                uint32_t hi, lo;
                split_pack(c[mf][nf][0], c[mf][nf][1], hi, lo);
                size_t idx = (size_t)(b * CC + row) * NN + col;
                *(uint32_t*)(g_vh + idx) = hi;
                *(uint32_t*)(g_vl + idx) = lo;
                split_pack(c[mf][nf][2], c[mf][nf][3], hi, lo);
                idx = (size_t)(b * CC + row + 8) * NN + col;
                *(uint32_t*)(g_vh + idx) = hi;
                *(uint32_t*)(g_vl + idx) = lo;
            }
    } else {
        // q/k: transpose via smem, split store [bh][i][d]
        float* ep = (float*)sm;
        #pragma unroll
        for (int mf = 0; mf < 2; mf++)
            #pragma unroll
            for (int nf = 0; nf < 8; nf++) {
                int ro = wm * 32 + mf * 16 + (lane >> 2);
                int cn = wn * 64 + nf * 8 + ((lane & 3) << 1);
                ep[cn * 132 + ro]           = c[mf][nf][0];
                ep[(cn + 1) * 132 + ro]     = c[mf][nf][1];
                ep[cn * 132 + ro + 8]       = c[mf][nf][2];
                ep[(cn + 1) * 132 + ro + 8] = c[mf][nf][3];
            }
        __syncthreads();
        __nv_bfloat16* oh = (mtx == 0) ? g_qh : g_kh;
        __nv_bfloat16* ol = (mtx == 0) ? g_ql : g_kl;
        int n = tid >> 1, half = tid & 1;
        int h = (o0 >> 6) + half;
        size_t base = ((size_t)(b * HH + h) * NN + n0 + n) * DD;
        #pragma unroll
        for (int d = 0; d < 64; d += 2) {
            float v0 = ep[n * 132 + half * 64 + d];
            float v1 = ep[n * 132 + half * 64 + d + 1];
            uint32_t hi, lo;
            split_pack(v0, v1, hi, lo);
            *(uint32_t*)(oh + base + d) = hi;
            *(uint32_t*)(ol + base + d) = lo;
        }
    }
}

// ---------------- Wo projection ----------------
__global__ __launch_bounds__(256) void proj_out_kernel(float* __restrict__ out)
{
    extern __shared__ char sm[];
    const int lane = threadIdx.x & 31, wid = threadIdx.x >> 5;
    const int wm = wid & 3, wn = wid >> 2;
    const int b = blockIdx.z;
    const int o0 = blockIdx.y << 7, n0 = blockIdx.x << 7;

    float c[2][8][4] = {};
    proj_gemm(g_wh + (size_t)3 * CC * CC, g_wl + (size_t)3 * CC * CC,
              g_yh + (size_t)b * NN * CC, g_yl + (size_t)b * NN * CC,
              o0, n0, sm, c);

    #pragma unroll
    for (int mf = 0; mf < 2; mf++)
        #pragma unroll
        for (int nf = 0; nf < 8; nf++) {
            int row = o0 + wm * 32 + mf * 16 + (lane >> 2);
            int col = n0 + wn * 64 + nf * 8 + ((lane & 3) << 1);
            *(float2*)(out + (size_t)(b * CC + row) * NN + col) =
                make_float2(c[mf][nf][0], c[mf][nf][1]);
            *(float2*)(out + (size_t)(b * CC + row + 8) * NN + col) =
                make_float2(c[mf][nf][2], c[mf][nf][3]);
        }
}

// ---------------- fused attention (FA2-style, register-resident P) ---------------
// Block 256 thr = 8 warps, each warp owns 16 i-rows. 2-stage K/V pipeline.
// smem: Q hi/lo @0/18432 (pitch 144), stages @36864 + s*71680:
//   KH +0 (128x144), KL +18432, VH +36864 (64x272), VL +54272
#define A_QH 0u
#define A_QL 18432u
#define A_ST 36864u
#define A_STSZ 71680u
#define ATTN_SMEM (36864 + 2 * 71680)   // 180224

__device__ __forceinline__ void attn_load_kv(uint32_t sb, int s, int bh, int b, int h, int j0)
{
    const int tid = threadIdx.x;
    uint32_t st = sb + A_ST + (uint32_t)s * A_STSZ;
    #pragma unroll
    for (int t = tid; t < 1024; t += 256) {
        int r = t >> 3, ch = t & 7;
        uint32_t d = (uint32_t)(r * 144 + ch * 16);
        size_t src = ((size_t)bh * NN + j0 + r) * DD + ch * 8;
        cp16(st + d,          g_kh + src);
        cp16(st + 18432u + d, g_kl + src);
    }
    #pragma unroll
    for (int t = tid; t < 1024; t += 256) {
        int r = t >> 4, ch = t & 15;
        uint32_t d = (uint32_t)(r * 272 + ch * 16);
        size_t src = (size_t)(b * CC + h * DD + r) * NN + j0 + ch * 8;
        cp16(st + 36864u + d, g_vh + src);
        cp16(st + 54272u + d, g_vl + src);
    }
}

__global__ __launch_bounds__(256) void attn_kernel()
{
    extern __shared__ char sm[];
    const int tid = threadIdx.x, lane = tid & 31, wid = tid >> 5;
    const int bh = blockIdx.y, b = bh >> 3, h = bh & 7;
    const int i0 = blockIdx.x << 7;
    const uint32_t sb = smem_u32(sm);

    // Q tile [128 i][64 d] hi/lo (group 0, together with jb=0 K/V)
    #pragma unroll
    for (int t = tid; t < 1024; t += 256) {
        int r = t >> 3, ch = t & 7;
        uint32_t d = (uint32_t)(r * 144 + ch * 16);
        size_t src = ((size_t)bh * NN + i0 + r) * DD + ch * 8;
        cp16(sb + A_QH + d, g_qh + src);
        cp16(sb + A_QL + d, g_ql + src);
    }
    attn_load_kv(sb, 0, bh, b, h, 0);
    CP_COMMIT();
    attn_load_kv(sb, 1, bh, b, h, 128);
    CP_COMMIT();

    float yc[8][4] = {};
    float rs0 = 0.f, rs1 = 0.f;
    uint32_t qfh[4][4], qfl[4][4];

    for (int jb = 0; jb < 8; jb++) {
        uint32_t st = sb + A_ST + (uint32_t)(jb & 1) * A_STSZ;
        CP_WAIT1();
        __syncthreads();
        if (jb == 0) {
            #pragma unroll
            for (int ks = 0; ks < 4; ks++) {
                ldmx4(qfh[ks], frag_addr(sb + A_QH, wid * 16, ks * 16, 144));
                ldmx4(qfl[ks], frag_addr(sb + A_QL, wid * 16, ks * 16, 144));
            }
        }

        // S = Q.K^T  (3xBF16): warp tile 16(i) x 128(j)
        float cs[16][4] = {};
        #pragma unroll
        for (int ks = 0; ks < 4; ks++) {
            #pragma unroll
            for (int g = 0; g < 8; g++) {
                uint32_t rh[4], rl[4];
                ldmx4(rh, frag_addr(st,           g * 16, ks * 16, 144));
                ldmx4(rl, frag_addr(st + 18432u,  g * 16, ks * 16, 144));
                #pragma unroll
                for (int t = 0; t < 2; t++) {
                    int nf = 2 * g + t;
                    mma16816(cs[nf], qfh[ks], rh[t], rh[t + 2]);
                    mma16816(cs[nf], qfh[ks], rl[t], rl[t + 2]);
                    mma16816(cs[nf], qfl[ks], rh[t], rh[t + 2]);
                }
            }
        }

        // exp + rowsum + repack P into A-fragments (registers only)
        uint32_t aph[8][4], apl[8][4];
        #pragma unroll
        for (int nf = 0; nf < 16; nf++) {
            float p0 = __expf(cs[nf][0]), p1 = __expf(cs[nf][1]);
            float p2 = __expf(cs[nf][2]), p3 = __expf(cs[nf][3]);
            rs0 += p0 + p1;
            rs1 += p2 + p3;
            uint32_t h01, l01, h23, l23;
            split_pack(p0, p1, h01, l01);
            split_pack(p2, p3, h23, l23);
            int ks = nf >> 1, base = (nf & 1) << 1;
            aph[ks][base] = h01; aph[ks][base + 1] = h23;
            apl[ks][base] = l01; apl[ks][base + 1] = l23;
        }

        // Y += P.V^T  (3xBF16): warp tile 16(i) x 64(d), k = 128 j
        #pragma unroll
        for (int ks = 0; ks < 8; ks++) {
            #pragma unroll
            for (int g = 0; g < 4; g++) {
                uint32_t rh[4], rl[4];
                ldmx4(rh, frag_addr(st + 36864u, g * 16, ks * 16, 272));
                ldmx4(rl, frag_addr(st + 54272u, g * 16, ks * 16, 272));
                #pragma unroll
                for (int t = 0; t < 2; t++) {
                    int nf = 2 * g + t;
                    mma16816(yc[nf], aph[ks], rh[t], rh[t + 2]);
                    mma16816(yc[nf], aph[ks], rl[t], rl[t + 2]);
                    mma16816(yc[nf], apl[ks], rh[t], rh[t + 2]);
                }
            }
        }
        __syncthreads();
        if (jb + 2 < 8) attn_load_kv(sb, jb & 1, bh, b, h, (jb + 2) * 128);
        CP_COMMIT();
    }

    // rowsum: quad reduction (each thread's rows are lane/4 and lane/4+8)
    rs0 += __shfl_xor_sync(0xffffffffu, rs0, 1);
    rs0 += __shfl_xor_sync(0xffffffffu, rs0, 2);
    rs1 += __shfl_xor_sync(0xffffffffu, rs1, 1);
    rs1 += __shfl_xor_sync(0xffffffffu, rs1, 2);
    float inv0 = 1.f / rs0, inv1 = 1.f / rs1;

    int row = i0 + wid * 16 + (lane >> 2);
    #pragma unroll
    for (int nf = 0; nf < 8; nf++) {
        int d = h * DD + nf * 8 + ((lane & 3) << 1);
        uint32_t hi, lo;
        split_pack(yc[nf][0] * inv0, yc[nf][1] * inv0, hi, lo);
        size_t idx = ((size_t)b * NN + row) * CC + d;
        *(uint32_t*)(g_yh + idx) = hi;
        *(uint32_t*)(g_yl + idx) = lo;
        split_pack(yc[nf][2] * inv1, yc[nf][3] * inv1, hi, lo);
        idx = ((size_t)b * NN + row + 8) * CC + d;
        *(uint32_t*)(g_yh + idx) = hi;
        *(uint32_t*)(g_yl + idx) = lo;
    }
}

// ---------------- entry ----------------------------------------------------------
extern "C" void kernel_launch(void* const* d_in, const int* in_sizes, int n_in,
                              void* d_out, int out_size)
{
    const float* x  = (const float*)d_in[0];
    const float* Wq = (const float*)d_in[1];
    const float* Wk = (const float*)d_in[2];
    const float* Wv = (const float*)d_in[3];
    const float* Wo = (const float*)d_in[4];
    float* out = (float*)d_out;

    cudaFuncSetAttribute(proj_qkv_kernel, cudaFuncAttributeMaxDynamicSharedMemorySize, PROJ_SMEM);
    cudaFuncSetAttribute(proj_out_kernel, cudaFuncAttributeMaxDynamicSharedMemorySize, PROJ_SMEM);
    cudaFuncSetAttribute(attn_kernel,     cudaFuncAttributeMaxDynamicSharedMemorySize, ATTN_SMEM);

    prep_w_kernel<<<dim3(CC * CC / 1024, 4), 256>>>(Wq, Wk, Wv, Wo);
    prep_x_kernel<<<dim3(NN / 32, CC / 32, BB), dim3(32, 8)>>>(x);
    proj_qkv_kernel<<<dim3(NN / 128, CC / 128, BB * 3), 256, PROJ_SMEM>>>();
    attn_kernel<<<dim3(NN / 128, BHH), 256, ATTN_SMEM>>>();
    proj_out_kernel<<<dim3(NN / 128, CC / 128, BB), 256, PROJ_SMEM>>>(out);
}

// round 6
// speedup vs baseline: 2.5107x; 1.0003x over previous
#include <cuda_runtime.h>
#include <cuda_bf16.h>
#include <cstdint>

#define BB 4
#define CC 512
#define NN 1024
#define HH 8
#define DD 64
#define BHH 32

// ---------------- bf16 hi/lo split scratch (device globals) ----------------
__device__ __nv_bfloat16 g_xh[BB * NN * CC], g_xl[BB * NN * CC];   // xT [b][n][c]
__device__ __nv_bfloat16 g_wh[4 * CC * CC],  g_wl[4 * CC * CC];    // Wq,Wk,Wv,Wo [o][c]
__device__ __nv_bfloat16 g_qh[BHH * NN * DD], g_ql[BHH * NN * DD]; // [bh][i][d]
__device__ __nv_bfloat16 g_kh[BHH * NN * DD], g_kl[BHH * NN * DD]; // [bh][j][d]
__device__ __nv_bfloat16 g_vh[BB * CC * NN],  g_vl[BB * CC * NN];  // [b][o][n] = [bh][d][j]
__device__ __nv_bfloat16 g_yh[BB * NN * CC],  g_yl[BB * NN * CC];  // yT [b][i][c]

// ================= helpers =================
__device__ __forceinline__ uint32_t smem_u32(const void* p) {
    uint32_t a;
    asm("{ .reg .u64 t; cvta.to.shared.u64 t, %1; cvt.u32.u64 %0, t; }" : "=r"(a) : "l"(p));
    return a;
}
__device__ __forceinline__ void cp16(uint32_t dst, const void* src) {
    asm volatile("cp.async.cg.shared.global [%0], [%1], 16;" :: "r"(dst), "l"(src));
}
#define CP_COMMIT()  asm volatile("cp.async.commit_group;")
#define CP_WAIT1()   asm volatile("cp.async.wait_group 1;")
__device__ __forceinline__ void ldmx4(uint32_t r[4], uint32_t addr) {
    asm volatile("ldmatrix.sync.aligned.m8n8.x4.shared.b16 {%0,%1,%2,%3}, [%4];"
                 : "=r"(r[0]), "=r"(r[1]), "=r"(r[2]), "=r"(r[3]) : "r"(addr));
}
__device__ __forceinline__ void mma16816(float c[4], const uint32_t a[4], uint32_t b0, uint32_t b1) {
    asm volatile(
        "mma.sync.aligned.m16n8k16.row.col.f32.bf16.bf16.f32 "
        "{%0,%1,%2,%3}, {%4,%5,%6,%7}, {%8,%9}, {%0,%1,%2,%3};"
        : "+f"(c[0]), "+f"(c[1]), "+f"(c[2]), "+f"(c[3])
        : "r"(a[0]), "r"(a[1]), "r"(a[2]), "r"(a[3]), "r"(b0), "r"(b1));
}
// ldmatrix source address for 16x16 tile at (row0, k0), pitch in bytes
__device__ __forceinline__ uint32_t frag_addr(uint32_t base, int row0, int k0, int pitchB) {
    int lane = threadIdx.x & 31;
    int m = lane >> 3, r = lane & 7;
    int row = row0 + ((m & 1) << 3) + r;
    int k = k0 + ((m >> 1) << 3);
    return base + (uint32_t)(row * pitchB + k * 2);
}
__device__ __forceinline__ void split_pack(float a, float b, uint32_t& hi, uint32_t& lo) {
    __nv_bfloat16 ha = __float2bfloat16(a), hb = __float2bfloat16(b);
    __nv_bfloat16 la = __float2bfloat16(a - __bfloat162float(ha));
    __nv_bfloat16 lb = __float2bfloat16(b - __bfloat162float(hb));
    hi = (uint32_t)__bfloat16_as_ushort(ha) | ((uint32_t)__bfloat16_as_ushort(hb) << 16);
    lo = (uint32_t)__bfloat16_as_ushort(la) | ((uint32_t)__bfloat16_as_ushort(lb) << 16);
}

// ---------------- prep kernels ----------------
__global__ __launch_bounds__(256) void prep_w_kernel(const float* __restrict__ Wq,
                                                     const float* __restrict__ Wk,
                                                     const float* __restrict__ Wv,
                                                     const float* __restrict__ Wo)
{
    int w = blockIdx.y;
    const float* W = (w == 0) ? Wq : (w == 1) ? Wk : (w == 2) ? Wv : Wo;
    int i = (blockIdx.x * 256 + threadIdx.x) * 4;
    float4 v = *(const float4*)(W + i);
    uint32_t h0, l0, h1, l1;
    split_pack(v.x, v.y, h0, l0);
    split_pack(v.z, v.w, h1, l1);
    size_t o = (size_t)w * CC * CC + i;
    *(uint2*)(g_wh + o) = make_uint2(h0, h1);
    *(uint2*)(g_wl + o) = make_uint2(l0, l1);
}

__global__ void prep_x_kernel(const float* __restrict__ x)
{
    __shared__ float t[32][33];
    int b = blockIdx.z;
    int n0 = blockIdx.x << 5, c0 = blockIdx.y << 5;
    int tx = threadIdx.x, ty = threadIdx.y;
    #pragma unroll
    for (int k = 0; k < 4; k++)
        t[ty + k * 8][tx] = x[((size_t)b * CC + c0 + ty + k * 8) * NN + n0 + tx];
    __syncthreads();
    #pragma unroll
    for (int k = 0; k < 4; k++) {
        int n = n0 + ty + k * 8;
        float v = t[tx][ty + k * 8];
        __nv_bfloat16 h = __float2bfloat16(v);
        __nv_bfloat16 l = __float2bfloat16(v - __bfloat162float(h));
        size_t idx = ((size_t)b * NN + n) * CC + c0 + tx;
        g_xh[idx] = h;
        g_xl[idx] = l;
    }
}

// ---------------- shared proj mainloop: c[2][8][4] += W-tile . X-tile ------------
// 2-stage cp.async pipeline. Stage = 40960B: AH@0 AL@10240 BH@20480 BL@30720.
#define PROJ_SMEM 81920

__device__ __forceinline__ void proj_load(uint32_t st,
                                          const __nv_bfloat16* Ah, const __nv_bfloat16* Al,
                                          const __nv_bfloat16* Bh, const __nv_bfloat16* Bl,
                                          int o0, int n0, int k0)
{
    const int tid = threadIdx.x;
    #pragma unroll
    for (int t = tid; t < 512; t += 256) {
        int r = t >> 2, ch = t & 3;
        uint32_t d = (uint32_t)(r * 80 + ch * 16);
        size_t sA = (size_t)(o0 + r) * CC + k0 + ch * 8;
        size_t sB = (size_t)(n0 + r) * CC + k0 + ch * 8;
        cp16(st + 0u     + d, Ah + sA);
        cp16(st + 10240u + d, Al + sA);
        cp16(st + 20480u + d, Bh + sB);
        cp16(st + 30720u + d, Bl + sB);
    }
}

__device__ void proj_gemm(const __nv_bfloat16* Ah, const __nv_bfloat16* Al,
                          const __nv_bfloat16* Bh, const __nv_bfloat16* Bl,
                          int o0, int n0, char* sm, float c[2][8][4])
{
    const int wid = threadIdx.x >> 5;
    const int wm = wid & 3, wn = wid >> 2;
    const uint32_t sb = smem_u32(sm);

    proj_load(sb,          Ah, Al, Bh, Bl, o0, n0, 0);
    CP_COMMIT();
    proj_load(sb + 40960u, Ah, Al, Bh, Bl, o0, n0, 32);
    CP_COMMIT();

    for (int kc = 0; kc < 16; kc++) {
        uint32_t st = sb + (uint32_t)(kc & 1) * 40960u;
        CP_WAIT1();
        __syncthreads();
        #pragma unroll
        for (int ks = 0; ks < 2; ks++) {
            uint32_t ah[2][4], al[2][4];
            ldmx4(ah[0], frag_addr(st + 0u,     wm * 32,      ks * 16, 80));
            ldmx4(ah[1], frag_addr(st + 0u,     wm * 32 + 16, ks * 16, 80));
            ldmx4(al[0], frag_addr(st + 10240u, wm * 32,      ks * 16, 80));
            ldmx4(al[1], frag_addr(st + 10240u, wm * 32 + 16, ks * 16, 80));
            // stream B fragments per 16-col group: low live-register count
            #pragma unroll
            for (int g = 0; g < 4; g++) {
                uint32_t rh[4], rl[4];
                ldmx4(rh, frag_addr(st + 20480u, wn * 64 + g * 16, ks * 16, 80));
                ldmx4(rl, frag_addr(st + 30720u, wn * 64 + g * 16, ks * 16, 80));
                #pragma unroll
                for (int t = 0; t < 2; t++) {
                    int nf = 2 * g + t;
                    #pragma unroll
                    for (int mf = 0; mf < 2; mf++) {
                        mma16816(c[mf][nf], ah[mf], rh[t], rh[t + 2]);
                        mma16816(c[mf][nf], ah[mf], rl[t], rl[t + 2]);
                        mma16816(c[mf][nf], al[mf], rh[t], rh[t + 2]);
                    }
                }
            }
        }
        __syncthreads();
        if (kc + 2 < 16) proj_load(st, Ah, Al, Bh, Bl, o0, n0, (kc + 2) * 32);
        CP_COMMIT();
    }
}

// ---------------- proj QKV ----------------
__global__ __launch_bounds__(256, 2) void proj_qkv_kernel()
{
    extern __shared__ char sm[];
    const int tid = threadIdx.x, lane = tid & 31, wid = tid >> 5;
    const int wm = wid & 3, wn = wid >> 2;
    const int z = blockIdx.z, b = z / 3, mtx = z - b * 3;  // 0=q 1=k 2=v
    const int o0 = blockIdx.y << 7, n0 = blockIdx.x << 7;

    float c[2][8][4] = {};
    proj_gemm(g_wh + (size_t)mtx * CC * CC, g_wl + (size_t)mtx * CC * CC,
              g_xh + (size_t)b * NN * CC, g_xl + (size_t)b * NN * CC,
              o0, n0, sm, c);

    if (mtx == 2) {
        // v: split store [b][o][n]
        #pragma unroll
        for (int mf = 0; mf < 2; mf++)
            #pragma unroll
            for (int nf = 0; nf < 8; nf++) {
                int row = o0 + wm * 32 + mf * 16 + (lane >> 2);
                int col = n0 + wn * 64 + nf * 8 + ((lane & 3) << 1);
                uint32_t hi, lo;
                split_pack(c[mf][nf][0], c[mf][nf][1], hi, lo);
                size_t idx = (size_t)(b * CC + row) * NN + col;
                *(uint32_t*)(g_vh + idx) = hi;
                *(uint32_t*)(g_vl + idx) = lo;
                split_pack(c[mf][nf][2], c[mf][nf][3], hi, lo);
                idx = (size_t)(b * CC + row + 8) * NN + col;
                *(uint32_t*)(g_vh + idx) = hi;
                *(uint32_t*)(g_vl + idx) = lo;
            }
    } else {
        // q/k: transpose via smem, split store [bh][i][d]
        float* ep = (float*)sm;
        __syncthreads();
        #pragma unroll
        for (int mf = 0; mf < 2; mf++)
            #pragma unroll
            for (int nf = 0; nf < 8; nf++) {
                int ro = wm * 32 + mf * 16 + (lane >> 2);
                int cn = wn * 64 + nf * 8 + ((lane & 3) << 1);
                ep[cn * 132 + ro]           = c[mf][nf][0];
                ep[(cn + 1) * 132 + ro]     = c[mf][nf][1];
                ep[cn * 132 + ro + 8]       = c[mf][nf][2];
                ep[(cn + 1) * 132 + ro + 8] = c[mf][nf][3];
            }
        __syncthreads();
        __nv_bfloat16* oh = (mtx == 0) ? g_qh : g_kh;
        __nv_bfloat16* ol = (mtx == 0) ? g_ql : g_kl;
        int n = tid >> 1, half = tid & 1;
        int h = (o0 >> 6) + half;
        size_t base = ((size_t)(b * HH + h) * NN + n0 + n) * DD;
        #pragma unroll
        for (int d = 0; d < 64; d += 2) {
            float v0 = ep[n * 132 + half * 64 + d];
            float v1 = ep[n * 132 + half * 64 + d + 1];
            uint32_t hi, lo;
            split_pack(v0, v1, hi, lo);
            *(uint32_t*)(oh + base + d) = hi;
            *(uint32_t*)(ol + base + d) = lo;
        }
    }
}

// ---------------- Wo projection ----------------
__global__ __launch_bounds__(256, 2) void proj_out_kernel(float* __restrict__ out)
{
    extern __shared__ char sm[];
    const int lane = threadIdx.x & 31, wid = threadIdx.x >> 5;
    const int wm = wid & 3, wn = wid >> 2;
    const int b = blockIdx.z;
    const int o0 = blockIdx.y << 7, n0 = blockIdx.x << 7;

    float c[2][8][4] = {};
    proj_gemm(g_wh + (size_t)3 * CC * CC, g_wl + (size_t)3 * CC * CC,
              g_yh + (size_t)b * NN * CC, g_yl + (size_t)b * NN * CC,
              o0, n0, sm, c);

    #pragma unroll
    for (int mf = 0; mf < 2; mf++)
        #pragma unroll
        for (int nf = 0; nf < 8; nf++) {
            int row = o0 + wm * 32 + mf * 16 + (lane >> 2);
            int col = n0 + wn * 64 + nf * 8 + ((lane & 3) << 1);
            *(float2*)(out + (size_t)(b * CC + row) * NN + col) =
                make_float2(c[mf][nf][0], c[mf][nf][1]);
            *(float2*)(out + (size_t)(b * CC + row + 8) * NN + col) =
                make_float2(c[mf][nf][2], c[mf][nf][3]);
        }
}

// ---------------- fused attention (FA2-style, register-resident P) ---------------
// Block 256 thr = 8 warps, each warp owns 16 i-rows. 2-stage K/V pipeline.
// Interleaved in 32-column j-groups to keep live registers low and overlap
// exp/cvt with tensor work.
// smem: Q hi/lo @0/18432 (pitch 144), stages @36864 + s*71680:
//   KH +0 (128x144), KL +18432, VH +36864 (64x272), VL +54272
#define A_QH 0u
#define A_QL 18432u
#define A_ST 36864u
#define A_STSZ 71680u
#define ATTN_SMEM (36864 + 2 * 71680)   // 180224

__device__ __forceinline__ void attn_load_kv(uint32_t sb, int s, int bh, int b, int h, int j0)
{
    const int tid = threadIdx.x;
    uint32_t st = sb + A_ST + (uint32_t)s * A_STSZ;
    #pragma unroll
    for (int t = tid; t < 1024; t += 256) {
        int r = t >> 3, ch = t & 7;
        uint32_t d = (uint32_t)(r * 144 + ch * 16);
        size_t src = ((size_t)bh * NN + j0 + r) * DD + ch * 8;
        cp16(st + d,          g_kh + src);
        cp16(st + 18432u + d, g_kl + src);
    }
    #pragma unroll
    for (int t = tid; t < 1024; t += 256) {
        int r = t >> 4, ch = t & 15;
        uint32_t d = (uint32_t)(r * 272 + ch * 16);
        size_t src = (size_t)(b * CC + h * DD + r) * NN + j0 + ch * 8;
        cp16(st + 36864u + d, g_vh + src);
        cp16(st + 54272u + d, g_vl + src);
    }
}

__global__ __launch_bounds__(256) void attn_kernel()
{
    extern __shared__ char sm[];
    const int tid = threadIdx.x, lane = tid & 31, wid = tid >> 5;
    const int bh = blockIdx.y, b = bh >> 3, h = bh & 7;
    const int i0 = blockIdx.x << 7;
    const uint32_t sb = smem_u32(sm);

    // Q tile [128 i][64 d] hi/lo (group 0, together with jb=0 K/V)
    #pragma unroll
    for (int t = tid; t < 1024; t += 256) {
        int r = t >> 3, ch = t & 7;
        uint32_t d = (uint32_t)(r * 144 + ch * 16);
        size_t src = ((size_t)bh * NN + i0 + r) * DD + ch * 8;
        cp16(sb + A_QH + d, g_qh + src);
        cp16(sb + A_QL + d, g_ql + src);
    }
    attn_load_kv(sb, 0, bh, b, h, 0);
    CP_COMMIT();
    attn_load_kv(sb, 1, bh, b, h, 128);
    CP_COMMIT();

    float yc[8][4] = {};
    float rs0 = 0.f, rs1 = 0.f;
    uint32_t qfh[4][4], qfl[4][4];

    for (int jb = 0; jb < 8; jb++) {
        uint32_t st = sb + A_ST + (uint32_t)(jb & 1) * A_STSZ;
        CP_WAIT1();
        __syncthreads();
        if (jb == 0) {
            #pragma unroll
            for (int ks = 0; ks < 4; ks++) {
                ldmx4(qfh[ks], frag_addr(sb + A_QH, wid * 16, ks * 16, 144));
                ldmx4(qfl[ks], frag_addr(sb + A_QL, wid * 16, ks * 16, 144));
            }
        }

        // process the 128-j block in four 32-column groups:
        // S (48 mma) -> exp/pack (16 exp) -> PV (48 mma) per group
        #pragma unroll
        for (int grp = 0; grp < 4; grp++) {
            // ---- S = Q.K^T for j in [grp*32, grp*32+32) ----
            float cs[4][4] = {};
            #pragma unroll
            for (int ksd = 0; ksd < 4; ksd++) {
                #pragma unroll
                for (int gg = 0; gg < 2; gg++) {
                    int g = 2 * grp + gg;
                    uint32_t rh[4], rl[4];
                    ldmx4(rh, frag_addr(st,          g * 16, ksd * 16, 144));
                    ldmx4(rl, frag_addr(st + 18432u, g * 16, ksd * 16, 144));
                    #pragma unroll
                    for (int t = 0; t < 2; t++) {
                        int nf = 2 * gg + t;
                        mma16816(cs[nf], qfh[ksd], rh[t], rh[t + 2]);
                        mma16816(cs[nf], qfh[ksd], rl[t], rl[t + 2]);
                        mma16816(cs[nf], qfl[ksd], rh[t], rh[t + 2]);
                    }
                }
            }
            // ---- exp + rowsum + repack into A-fragments ----
            uint32_t aph[2][4], apl[2][4];
            #pragma unroll
            for (int nf = 0; nf < 4; nf++) {
                float p0 = __expf(cs[nf][0]), p1 = __expf(cs[nf][1]);
                float p2 = __expf(cs[nf][2]), p3 = __expf(cs[nf][3]);
                rs0 += p0 + p1;
                rs1 += p2 + p3;
                uint32_t h01, l01, h23, l23;
                split_pack(p0, p1, h01, l01);
                split_pack(p2, p3, h23, l23);
                int kk = nf >> 1, base = (nf & 1) << 1;
                aph[kk][base] = h01; aph[kk][base + 1] = h23;
                apl[kk][base] = l01; apl[kk][base + 1] = l23;
            }
            // ---- Y += P.V^T for k(=j) in this group ----
            #pragma unroll
            for (int kk = 0; kk < 2; kk++) {
                int ks = 2 * grp + kk;
                #pragma unroll
                for (int gv = 0; gv < 4; gv++) {
                    uint32_t rh[4], rl[4];
                    ldmx4(rh, frag_addr(st + 36864u, gv * 16, ks * 16, 272));
                    ldmx4(rl, frag_addr(st + 54272u, gv * 16, ks * 16, 272));
                    #pragma unroll
                    for (int t = 0; t < 2; t++) {
                        int nf = 2 * gv + t;
                        mma16816(yc[nf], aph[kk], rh[t], rh[t + 2]);
                        mma16816(yc[nf], aph[kk], rl[t], rl[t + 2]);
                        mma16816(yc[nf], apl[kk], rh[t], rh[t + 2]);
                    }
                }
            }
        }
        __syncthreads();
        if (jb + 2 < 8) attn_load_kv(sb, jb & 1, bh, b, h, (jb + 2) * 128);
        CP_COMMIT();
    }

    // rowsum: quad reduction (each thread's rows are lane/4 and lane/4+8)
    rs0 += __shfl_xor_sync(0xffffffffu, rs0, 1);
    rs0 += __shfl_xor_sync(0xffffffffu, rs0, 2);
    rs1 += __shfl_xor_sync(0xffffffffu, rs1, 1);
    rs1 += __shfl_xor_sync(0xffffffffu, rs1, 2);
    float inv0 = 1.f / rs0, inv1 = 1.f / rs1;

    int row = i0 + wid * 16 + (lane >> 2);
    #pragma unroll
    for (int nf = 0; nf < 8; nf++) {
        int d = h * DD + nf * 8 + ((lane & 3) << 1);
        uint32_t hi, lo;
        split_pack(yc[nf][0] * inv0, yc[nf][1] * inv0, hi, lo);
        size_t idx = ((size_t)b * NN + row) * CC + d;
        *(uint32_t*)(g_yh + idx) = hi;
        *(uint32_t*)(g_yl + idx) = lo;
        split_pack(yc[nf][2] * inv1, yc[nf][3] * inv1, hi, lo);
        idx = ((size_t)b * NN + row + 8) * CC + d;
        *(uint32_t*)(g_yh + idx) = hi;
        *(uint32_t*)(g_yl + idx) = lo;
    }
}

// ---------------- entry ----------------------------------------------------------
extern "C" void kernel_launch(void* const* d_in, const int* in_sizes, int n_in,
                              void* d_out, int out_size)
{
    const float* x  = (const float*)d_in[0];
    const float* Wq = (const float*)d_in[1];
    const float* Wk = (const float*)d_in[2];
    const float* Wv = (const float*)d_in[3];
    const float* Wo = (const float*)d_in[4];
    float* out = (float*)d_out;

    cudaFuncSetAttribute(proj_qkv_kernel, cudaFuncAttributeMaxDynamicSharedMemorySize, PROJ_SMEM);
    cudaFuncSetAttribute(proj_out_kernel, cudaFuncAttributeMaxDynamicSharedMemorySize, PROJ_SMEM);
    cudaFuncSetAttribute(attn_kernel,     cudaFuncAttributeMaxDynamicSharedMemorySize, ATTN_SMEM);

    prep_w_kernel<<<dim3(CC * CC / 1024, 4), 256>>>(Wq, Wk, Wv, Wo);
    prep_x_kernel<<<dim3(NN / 32, CC / 32, BB), dim3(32, 8)>>>(x);
    proj_qkv_kernel<<<dim3(NN / 128, CC / 128, BB * 3), 256, PROJ_SMEM>>>();
    attn_kernel<<<dim3(NN / 128, BHH), 256, ATTN_SMEM>>>();
    proj_out_kernel<<<dim3(NN / 128, CC / 128, BB), 256, PROJ_SMEM>>>(out);
}

// round 7
// speedup vs baseline: 3.0149x; 1.2009x over previous
#include <cuda_runtime.h>
#include <cuda_bf16.h>
#include <cstdint>

#define BB 4
#define CC 512
#define NN 1024
#define HH 8
#define DD 64
#define BHH 32

// ---------------- bf16 hi/lo split scratch (device globals) ----------------
__device__ __nv_bfloat16 g_xh[BB * NN * CC], g_xl[BB * NN * CC];   // xT [b][n][c]
__device__ __nv_bfloat16 g_wh[4 * CC * CC],  g_wl[4 * CC * CC];    // Wq,Wk,Wv,Wo [o][c]
__device__ __nv_bfloat16 g_qh[BHH * NN * DD], g_ql[BHH * NN * DD]; // [bh][i][d]
__device__ __nv_bfloat16 g_kh[BHH * NN * DD], g_kl[BHH * NN * DD]; // [bh][j][d]
__device__ __nv_bfloat16 g_vh[BB * CC * NN],  g_vl[BB * CC * NN];  // [b][o][n] = [bh][d][j]
__device__ __nv_bfloat16 g_yh[BB * NN * CC],  g_yl[BB * NN * CC];  // yT [b][i][c]

// ================= helpers =================
__device__ __forceinline__ uint32_t smem_u32(const void* p) {
    uint32_t a;
    asm("{ .reg .u64 t; cvta.to.shared.u64 t, %1; cvt.u32.u64 %0, t; }" : "=r"(a) : "l"(p));
    return a;
}
__device__ __forceinline__ void cp16(uint32_t dst, const void* src) {
    asm volatile("cp.async.cg.shared.global [%0], [%1], 16;" :: "r"(dst), "l"(src));
}
#define CP_COMMIT()  asm volatile("cp.async.commit_group;")
#define CP_WAIT1()   asm volatile("cp.async.wait_group 1;")
__device__ __forceinline__ void ldmx4(uint32_t r[4], uint32_t addr) {
    asm volatile("ldmatrix.sync.aligned.m8n8.x4.shared.b16 {%0,%1,%2,%3}, [%4];"
                 : "=r"(r[0]), "=r"(r[1]), "=r"(r[2]), "=r"(r[3]) : "r"(addr));
}
__device__ __forceinline__ void mma16816(float c[4], const uint32_t a[4], uint32_t b0, uint32_t b1) {
    asm volatile(
        "mma.sync.aligned.m16n8k16.row.col.f32.bf16.bf16.f32 "
        "{%0,%1,%2,%3}, {%4,%5,%6,%7}, {%8,%9}, {%0,%1,%2,%3};"
        : "+f"(c[0]), "+f"(c[1]), "+f"(c[2]), "+f"(c[3])
        : "r"(a[0]), "r"(a[1]), "r"(a[2]), "r"(a[3]), "r"(b0), "r"(b1));
}
// ldmatrix source address for 16x16 tile at (row0, k0), pitch in bytes
__device__ __forceinline__ uint32_t frag_addr(uint32_t base, int row0, int k0, int pitchB) {
    int lane = threadIdx.x & 31;
    int m = lane >> 3, r = lane & 7;
    int row = row0 + ((m & 1) << 3) + r;
    int k = k0 + ((m >> 1) << 3);
    return base + (uint32_t)(row * pitchB + k * 2);
}
__device__ __forceinline__ void split_pack(float a, float b, uint32_t& hi, uint32_t& lo) {
    __nv_bfloat16 ha = __float2bfloat16(a), hb = __float2bfloat16(b);
    __nv_bfloat16 la = __float2bfloat16(a - __bfloat162float(ha));
    __nv_bfloat16 lb = __float2bfloat16(b - __bfloat162float(hb));
    hi = (uint32_t)__bfloat16_as_ushort(ha) | ((uint32_t)__bfloat16_as_ushort(hb) << 16);
    lo = (uint32_t)__bfloat16_as_ushort(la) | ((uint32_t)__bfloat16_as_ushort(lb) << 16);
}

// ---------------- prep kernels ----------------
__global__ __launch_bounds__(256) void prep_w_kernel(const float* __restrict__ Wq,
                                                     const float* __restrict__ Wk,
                                                     const float* __restrict__ Wv,
                                                     const float* __restrict__ Wo)
{
    int w = blockIdx.y;
    const float* W = (w == 0) ? Wq : (w == 1) ? Wk : (w == 2) ? Wv : Wo;
    int i = (blockIdx.x * 256 + threadIdx.x) * 4;
    float4 v = *(const float4*)(W + i);
    uint32_t h0, l0, h1, l1;
    split_pack(v.x, v.y, h0, l0);
    split_pack(v.z, v.w, h1, l1);
    size_t o = (size_t)w * CC * CC + i;
    *(uint2*)(g_wh + o) = make_uint2(h0, h1);
    *(uint2*)(g_wl + o) = make_uint2(l0, l1);
}

__global__ void prep_x_kernel(const float* __restrict__ x)
{
    __shared__ float t[32][33];
    int b = blockIdx.z;
    int n0 = blockIdx.x << 5, c0 = blockIdx.y << 5;
    int tx = threadIdx.x, ty = threadIdx.y;
    #pragma unroll
    for (int k = 0; k < 4; k++)
        t[ty + k * 8][tx] = x[((size_t)b * CC + c0 + ty + k * 8) * NN + n0 + tx];
    __syncthreads();
    #pragma unroll
    for (int k = 0; k < 4; k++) {
        int n = n0 + ty + k * 8;
        float v = t[tx][ty + k * 8];
        __nv_bfloat16 h = __float2bfloat16(v);
        __nv_bfloat16 l = __float2bfloat16(v - __bfloat162float(h));
        size_t idx = ((size_t)b * NN + n) * CC + c0 + tx;
        g_xh[idx] = h;
        g_xl[idx] = l;
    }
}

// ---------------- shared proj mainloop: c[2][8][4] += W-tile . X-tile ------------
// 2-stage cp.async pipeline. Stage = 40960B: AH@0 AL@10240 BH@20480 BL@30720.
#define PROJ_SMEM 81920

__device__ __forceinline__ void proj_load(uint32_t st,
                                          const __nv_bfloat16* Ah, const __nv_bfloat16* Al,
                                          const __nv_bfloat16* Bh, const __nv_bfloat16* Bl,
                                          int o0, int n0, int k0)
{
    const int tid = threadIdx.x;
    #pragma unroll
    for (int t = tid; t < 512; t += 256) {
        int r = t >> 2, ch = t & 3;
        uint32_t d = (uint32_t)(r * 80 + ch * 16);
        size_t sA = (size_t)(o0 + r) * CC + k0 + ch * 8;
        size_t sB = (size_t)(n0 + r) * CC + k0 + ch * 8;
        cp16(st + 0u     + d, Ah + sA);
        cp16(st + 10240u + d, Al + sA);
        cp16(st + 20480u + d, Bh + sB);
        cp16(st + 30720u + d, Bl + sB);
    }
}

__device__ void proj_gemm(const __nv_bfloat16* Ah, const __nv_bfloat16* Al,
                          const __nv_bfloat16* Bh, const __nv_bfloat16* Bl,
                          int o0, int n0, char* sm, float c[2][8][4])
{
    const int wid = threadIdx.x >> 5;
    const int wm = wid & 3, wn = wid >> 2;
    const uint32_t sb = smem_u32(sm);

    proj_load(sb,          Ah, Al, Bh, Bl, o0, n0, 0);
    CP_COMMIT();
    proj_load(sb + 40960u, Ah, Al, Bh, Bl, o0, n0, 32);
    CP_COMMIT();

    for (int kc = 0; kc < 16; kc++) {
        uint32_t st = sb + (uint32_t)(kc & 1) * 40960u;
        CP_WAIT1();
        __syncthreads();
        #pragma unroll
        for (int ks = 0; ks < 2; ks++) {
            uint32_t ah[2][4], al[2][4];
            ldmx4(ah[0], frag_addr(st + 0u,     wm * 32,      ks * 16, 80));
            ldmx4(ah[1], frag_addr(st + 0u,     wm * 32 + 16, ks * 16, 80));
            ldmx4(al[0], frag_addr(st + 10240u, wm * 32,      ks * 16, 80));
            ldmx4(al[1], frag_addr(st + 10240u, wm * 32 + 16, ks * 16, 80));
            // stream B fragments per 16-col group: low live-register count
            #pragma unroll
            for (int g = 0; g < 4; g++) {
                uint32_t rh[4], rl[4];
                ldmx4(rh, frag_addr(st + 20480u, wn * 64 + g * 16, ks * 16, 80));
                ldmx4(rl, frag_addr(st + 30720u, wn * 64 + g * 16, ks * 16, 80));
                #pragma unroll
                for (int t = 0; t < 2; t++) {
                    int nf = 2 * g + t;
                    #pragma unroll
                    for (int mf = 0; mf < 2; mf++) {
                        mma16816(c[mf][nf], ah[mf], rh[t], rh[t + 2]);
                        mma16816(c[mf][nf], ah[mf], rl[t], rl[t + 2]);
                        mma16816(c[mf][nf], al[mf], rh[t], rh[t + 2]);
                    }
                }
            }
        }
        __syncthreads();
        if (kc + 2 < 16) proj_load(st, Ah, Al, Bh, Bl, o0, n0, (kc + 2) * 32);
        CP_COMMIT();
    }
}

// ---------------- proj QKV ----------------
__global__ __launch_bounds__(256, 2) void proj_qkv_kernel()
{
    extern __shared__ char sm[];
    const int tid = threadIdx.x, lane = tid & 31, wid = tid >> 5;
    const int wm = wid & 3, wn = wid >> 2;
    const int z = blockIdx.z, b = z / 3, mtx = z - b * 3;  // 0=q 1=k 2=v
    const int o0 = blockIdx.y << 7, n0 = blockIdx.x << 7;

    float c[2][8][4] = {};
    proj_gemm(g_wh + (size_t)mtx * CC * CC, g_wl + (size_t)mtx * CC * CC,
              g_xh + (size_t)b * NN * CC, g_xl + (size_t)b * NN * CC,
              o0, n0, sm, c);

    if (mtx == 2) {
        // v: split store [b][o][n]
        #pragma unroll
        for (int mf = 0; mf < 2; mf++)
            #pragma unroll
            for (int nf = 0; nf < 8; nf++) {
                int row = o0 + wm * 32 + mf * 16 + (lane >> 2);
                int col = n0 + wn * 64 + nf * 8 + ((lane & 3) << 1);
                uint32_t hi, lo;
                split_pack(c[mf][nf][0], c[mf][nf][1], hi, lo);
                size_t idx = (size_t)(b * CC + row) * NN + col;
                *(uint32_t*)(g_vh + idx) = hi;
                *(uint32_t*)(g_vl + idx) = lo;
                split_pack(c[mf][nf][2], c[mf][nf][3], hi, lo);
                idx = (size_t)(b * CC + row + 8) * NN + col;
                *(uint32_t*)(g_vh + idx) = hi;
                *(uint32_t*)(g_vl + idx) = lo;
            }
    } else {
        // q/k: transpose via smem, then fully-coalesced split store [bh][i][d]
        float* ep = (float*)sm;
        __syncthreads();
        #pragma unroll
        for (int mf = 0; mf < 2; mf++)
            #pragma unroll
            for (int nf = 0; nf < 8; nf++) {
                int ro = wm * 32 + mf * 16 + (lane >> 2);
                int cn = wn * 64 + nf * 8 + ((lane & 3) << 1);
                ep[cn * 132 + ro]           = c[mf][nf][0];
                ep[(cn + 1) * 132 + ro]     = c[mf][nf][1];
                ep[cn * 132 + ro + 8]       = c[mf][nf][2];
                ep[(cn + 1) * 132 + ro + 8] = c[mf][nf][3];
            }
        __syncthreads();
        __nv_bfloat16* oh = (mtx == 0) ? g_qh : g_kh;
        __nv_bfloat16* ol = (mtx == 0) ? g_ql : g_kl;
        // 8 lanes cover one output row's 64-d range as uint4 chunks (coalesced 128B)
        int chunk = tid & 7;
        #pragma unroll
        for (int it = 0; it < 8; it++) {
            int pr = (tid >> 3) + it * 32;    // 0..255 -> (row, head-half)
            int cn = pr >> 1, half = pr & 1;
            int hh = (o0 >> 6) + half;
            uint32_t vh4[4], vl4[4];
            #pragma unroll
            for (int e = 0; e < 4; e++) {
                float v0 = ep[cn * 132 + half * 64 + chunk * 8 + 2 * e];
                float v1 = ep[cn * 132 + half * 64 + chunk * 8 + 2 * e + 1];
                split_pack(v0, v1, vh4[e], vl4[e]);
            }
            size_t base = ((size_t)(b * HH + hh) * NN + n0 + cn) * DD + chunk * 8;
            *(uint4*)(oh + base) = make_uint4(vh4[0], vh4[1], vh4[2], vh4[3]);
            *(uint4*)(ol + base) = make_uint4(vl4[0], vl4[1], vl4[2], vl4[3]);
        }
    }
}

// ---------------- Wo projection ----------------
__global__ __launch_bounds__(256, 2) void proj_out_kernel(float* __restrict__ out)
{
    extern __shared__ char sm[];
    const int lane = threadIdx.x & 31, wid = threadIdx.x >> 5;
    const int wm = wid & 3, wn = wid >> 2;
    const int b = blockIdx.z;
    const int o0 = blockIdx.y << 7, n0 = blockIdx.x << 7;

    float c[2][8][4] = {};
    proj_gemm(g_wh + (size_t)3 * CC * CC, g_wl + (size_t)3 * CC * CC,
              g_yh + (size_t)b * NN * CC, g_yl + (size_t)b * NN * CC,
              o0, n0, sm, c);

    #pragma unroll
    for (int mf = 0; mf < 2; mf++)
        #pragma unroll
        for (int nf = 0; nf < 8; nf++) {
            int row = o0 + wm * 32 + mf * 16 + (lane >> 2);
            int col = n0 + wn * 64 + nf * 8 + ((lane & 3) << 1);
            *(float2*)(out + (size_t)(b * CC + row) * NN + col) =
                make_float2(c[mf][nf][0], c[mf][nf][1]);
            *(float2*)(out + (size_t)(b * CC + row + 8) * NN + col) =
                make_float2(c[mf][nf][2], c[mf][nf][3]);
        }
}

// ---------------- fused attention (FA2-style, register-resident P) ---------------
// Block 256 thr = 8 warps, each warp owns 16 i-rows. 2-stage 64-j K/V pipeline.
// smem: Q hi/lo @0/18432 (pitch 144), stages @36864 + s*36864:
//   KH +0 (64x144), KL +9216, VH +18432 (64x144), VL +27648
// Total 108 KB -> 2 CTAs/SM with regs<=128.
#define A_QH 0u
#define A_QL 18432u
#define A_ST 36864u
#define A_STSZ 36864u
#define ATTN_SMEM (36864 + 2 * 36864)   // 110592

__device__ __forceinline__ void attn_load_kv(uint32_t sb, int s, int bh, int b, int h, int j0)
{
    const int tid = threadIdx.x;
    uint32_t st = sb + A_ST + (uint32_t)s * A_STSZ;
    #pragma unroll
    for (int t = tid; t < 512; t += 256) {
        int r = t >> 3, ch = t & 7;
        uint32_t d = (uint32_t)(r * 144 + ch * 16);
        size_t srcK = ((size_t)bh * NN + j0 + r) * DD + ch * 8;
        cp16(st + d,          g_kh + srcK);
        cp16(st + 9216u + d,  g_kl + srcK);
        size_t srcV = (size_t)(b * CC + h * DD + r) * NN + j0 + ch * 8;
        cp16(st + 18432u + d, g_vh + srcV);
        cp16(st + 27648u + d, g_vl + srcV);
    }
}

__global__ __launch_bounds__(256, 2) void attn_kernel()
{
    extern __shared__ char sm[];
    const int tid = threadIdx.x, lane = tid & 31, wid = tid >> 5;
    const int bh = blockIdx.y, b = bh >> 3, h = bh & 7;
    const int i0 = blockIdx.x << 7;
    const uint32_t sb = smem_u32(sm);

    // Q tile [128 i][64 d] hi/lo (group 0, together with jb=0 K/V)
    #pragma unroll
    for (int t = tid; t < 1024; t += 256) {
        int r = t >> 3, ch = t & 7;
        uint32_t d = (uint32_t)(r * 144 + ch * 16);
        size_t src = ((size_t)bh * NN + i0 + r) * DD + ch * 8;
        cp16(sb + A_QH + d, g_qh + src);
        cp16(sb + A_QL + d, g_ql + src);
    }
    attn_load_kv(sb, 0, bh, b, h, 0);
    CP_COMMIT();
    attn_load_kv(sb, 1, bh, b, h, 64);
    CP_COMMIT();

    float yc[8][4] = {};
    float rs0 = 0.f, rs1 = 0.f;
    uint32_t qfh[4][4], qfl[4][4];

    for (int jb = 0; jb < 16; jb++) {
        uint32_t st = sb + A_ST + (uint32_t)(jb & 1) * A_STSZ;
        CP_WAIT1();
        __syncthreads();
        if (jb == 0) {
            #pragma unroll
            for (int ks = 0; ks < 4; ks++) {
                ldmx4(qfh[ks], frag_addr(sb + A_QH, wid * 16, ks * 16, 144));
                ldmx4(qfl[ks], frag_addr(sb + A_QL, wid * 16, ks * 16, 144));
            }
        }

        // process the 64-j block in two 32-column groups:
        // S -> exp/pack -> PV per group (keeps live registers low)
        #pragma unroll
        for (int grp = 0; grp < 2; grp++) {
            // ---- S = Q.K^T for j in [grp*32, grp*32+32) ----
            float cs[4][4] = {};
            #pragma unroll
            for (int ksd = 0; ksd < 4; ksd++) {
                #pragma unroll
                for (int gg = 0; gg < 2; gg++) {
                    int g = 2 * grp + gg;
                    uint32_t rh[4], rl[4];
                    ldmx4(rh, frag_addr(st,          g * 16, ksd * 16, 144));
                    ldmx4(rl, frag_addr(st + 9216u,  g * 16, ksd * 16, 144));
                    #pragma unroll
                    for (int t = 0; t < 2; t++) {
                        int nf = 2 * gg + t;
                        mma16816(cs[nf], qfh[ksd], rh[t], rh[t + 2]);
                        mma16816(cs[nf], qfh[ksd], rl[t], rl[t + 2]);
                        mma16816(cs[nf], qfl[ksd], rh[t], rh[t + 2]);
                    }
                }
            }
            // ---- exp + rowsum + repack into A-fragments ----
            uint32_t aph[2][4], apl[2][4];
            #pragma unroll
            for (int nf = 0; nf < 4; nf++) {
                float p0 = __expf(cs[nf][0]), p1 = __expf(cs[nf][1]);
                float p2 = __expf(cs[nf][2]), p3 = __expf(cs[nf][3]);
                rs0 += p0 + p1;
                rs1 += p2 + p3;
                uint32_t h01, l01, h23, l23;
                split_pack(p0, p1, h01, l01);
                split_pack(p2, p3, h23, l23);
                int kk = nf >> 1, base = (nf & 1) << 1;
                aph[kk][base] = h01; aph[kk][base + 1] = h23;
                apl[kk][base] = l01; apl[kk][base + 1] = l23;
            }
            // ---- Y += P.V^T for k(=j) in this group ----
            #pragma unroll
            for (int kk = 0; kk < 2; kk++) {
                int ks = 2 * grp + kk;
                #pragma unroll
                for (int gv = 0; gv < 4; gv++) {
                    uint32_t rh[4], rl[4];
                    ldmx4(rh, frag_addr(st + 18432u, gv * 16, ks * 16, 144));
                    ldmx4(rl, frag_addr(st + 27648u, gv * 16, ks * 16, 144));
                    #pragma unroll
                    for (int t = 0; t < 2; t++) {
                        int nf = 2 * gv + t;
                        mma16816(yc[nf], aph[kk], rh[t], rh[t + 2]);
                        mma16816(yc[nf], aph[kk], rl[t], rl[t + 2]);
                        mma16816(yc[nf], apl[kk], rh[t], rh[t + 2]);
                    }
                }
            }
        }
        __syncthreads();
        if (jb + 2 < 16) attn_load_kv(sb, jb & 1, bh, b, h, (jb + 2) * 64);
        CP_COMMIT();
    }

    // rowsum: quad reduction (each thread's rows are lane/4 and lane/4+8)
    rs0 += __shfl_xor_sync(0xffffffffu, rs0, 1);
    rs0 += __shfl_xor_sync(0xffffffffu, rs0, 2);
    rs1 += __shfl_xor_sync(0xffffffffu, rs1, 1);
    rs1 += __shfl_xor_sync(0xffffffffu, rs1, 2);
    float inv0 = 1.f / rs0, inv1 = 1.f / rs1;

    int row = i0 + wid * 16 + (lane >> 2);
    #pragma unroll
    for (int nf = 0; nf < 8; nf++) {
        int d = h * DD + nf * 8 + ((lane & 3) << 1);
        uint32_t hi, lo;
        split_pack(yc[nf][0] * inv0, yc[nf][1] * inv0, hi, lo);
        size_t idx = ((size_t)b * NN + row) * CC + d;
        *(uint32_t*)(g_yh + idx) = hi;
        *(uint32_t*)(g_yl + idx) = lo;
        split_pack(yc[nf][2] * inv1, yc[nf][3] * inv1, hi, lo);
        idx = ((size_t)b * NN + row + 8) * CC + d;
        *(uint32_t*)(g_yh + idx) = hi;
        *(uint32_t*)(g_yl + idx) = lo;
    }
}

// ---------------- entry ----------------------------------------------------------
extern "C" void kernel_launch(void* const* d_in, const int* in_sizes, int n_in,
                              void* d_out, int out_size)
{
    const float* x  = (const float*)d_in[0];
    const float* Wq = (const float*)d_in[1];
    const float* Wk = (const float*)d_in[2];
    const float* Wv = (const float*)d_in[3];
    const float* Wo = (const float*)d_in[4];
    float* out = (float*)d_out;

    cudaFuncSetAttribute(proj_qkv_kernel, cudaFuncAttributeMaxDynamicSharedMemorySize, PROJ_SMEM);
    cudaFuncSetAttribute(proj_out_kernel, cudaFuncAttributeMaxDynamicSharedMemorySize, PROJ_SMEM);
    cudaFuncSetAttribute(attn_kernel,     cudaFuncAttributeMaxDynamicSharedMemorySize, ATTN_SMEM);

    prep_w_kernel<<<dim3(CC * CC / 1024, 4), 256>>>(Wq, Wk, Wv, Wo);
    prep_x_kernel<<<dim3(NN / 32, CC / 32, BB), dim3(32, 8)>>>(x);
    proj_qkv_kernel<<<dim3(NN / 128, CC / 128, BB * 3), 256, PROJ_SMEM>>>();
    attn_kernel<<<dim3(NN / 128, BHH), 256, ATTN_SMEM>>>();
    proj_out_kernel<<<dim3(NN / 128, CC / 128, BB), 256, PROJ_SMEM>>>(out);
}